// round 1
// baseline (speedup 1.0000x reference)
#include <cuda_runtime.h>
#include <math.h>

#define NN 512
#define DD 128
#define NP (NN*NN)        // 262144 pixels
// scratch (static __device__ per harness rules)
__device__ float g_zl[(size_t)NP*DD];   // layernormed input, pixel-major [p][d]
__device__ float g_a [(size_t)DD*NP];   // a, head-major [h][i*N+k]
__device__ float g_b [(size_t)DD*NP];   // b, head-major [h][j*N+k]
__device__ float g_x [(size_t)DD*NP];   // triangle result, head-major [h][i*N+j]

// ---------------------------------------------------------------------------
// Kernel A: input LayerNorm over D=128. One warp per pixel.
// ---------------------------------------------------------------------------
__global__ void ln_in_kernel(const float* __restrict__ z,
                             const float* __restrict__ lnw,
                             const float* __restrict__ lnb) {
    int warp = threadIdx.x >> 5;
    int lane = threadIdx.x & 31;
    int p = blockIdx.x * 8 + warp;
    const float4* zin = (const float4*)(z + (size_t)p * DD);
    float4 v = zin[lane];
    float s  = v.x + v.y + v.z + v.w;
    float sq = v.x*v.x + v.y*v.y + v.z*v.z + v.w*v.w;
    #pragma unroll
    for (int o = 16; o > 0; o >>= 1) {
        s  += __shfl_xor_sync(0xffffffffu, s,  o);
        sq += __shfl_xor_sync(0xffffffffu, sq, o);
    }
    float mean = s * (1.0f/128.0f);
    float var  = sq * (1.0f/128.0f) - mean*mean;
    float rs   = rsqrtf(var + 1e-5f);
    float4 wv = ((const float4*)lnw)[lane];
    float4 bv = ((const float4*)lnb)[lane];
    float4 o4;
    o4.x = (v.x-mean)*rs*wv.x + bv.x;
    o4.y = (v.y-mean)*rs*wv.y + bv.y;
    o4.z = (v.z-mean)*rs*wv.z + bv.z;
    o4.w = (v.w-mean)*rs*wv.w + bv.w;
    ((float4*)(g_zl + (size_t)p*DD))[lane] = o4;
}

// ---------------------------------------------------------------------------
// Kernel B: projection GEMM  C[p,O] = zl[p,:] . Wrow(O)  with fused epilogue.
// Virtual weight matrix rows O: 0..127 = w_g; 128+2t = w_ab_p[t]; 129+2t = w_ab_g[t].
// Block tile 128 pixels x 128 outputs, K=128, BK=8, 256 threads, 8x8/thread.
// Epilogue: by==0 -> gate logits g (straight to d_out).
//           by>0  -> pairs (p,g): val=(p+bp)*m*sigmoid(g+bg); staged through
//                    smem then written coalesced, head-major, into g_a / g_b.
// ---------------------------------------------------------------------------
__global__ __launch_bounds__(256)
void proj_kernel(const float* __restrict__ mask,
                 const float* __restrict__ w_ab_p, const float* __restrict__ b_ab_p,
                 const float* __restrict__ w_ab_g, const float* __restrict__ b_ab_g,
                 const float* __restrict__ w_g,
                 float* __restrict__ out_g) {
    __shared__ float sh[64*132];              // overlaid: As(8x132) + Bs(8x132) | val(64x132)
    float* As = sh;                           // [8][132]
    float* Bs = sh + 8*132;                   // [8][132]

    int tid = threadIdx.x;
    int pBase = blockIdx.x * 128;
    int oBase = blockIdx.y * 128;

    int lrow = tid >> 1;
    int lk   = (tid & 1) * 4;
    const float* arow = g_zl + (size_t)(pBase + lrow) * DD;
    const float* wrow;
    {
        int O = oBase + lrow;
        if (O < 128) wrow = w_g + O * DD;
        else {
            int t = (O - 128) >> 1;
            wrow = ((O - 128) & 1) ? (w_ab_g + t * DD) : (w_ab_p + t * DD);
        }
    }

    float acc[8][8];
    #pragma unroll
    for (int i = 0; i < 8; i++)
        #pragma unroll
        for (int j = 0; j < 8; j++) acc[i][j] = 0.f;

    int m0 = (tid >> 4) * 8;
    int n0 = (tid & 15) * 8;

    for (int k0 = 0; k0 < DD; k0 += 8) {
        float4 av = *(const float4*)(arow + k0 + lk);
        float4 bv = *(const float4*)(wrow + k0 + lk);
        As[(lk+0)*132 + lrow] = av.x; As[(lk+1)*132 + lrow] = av.y;
        As[(lk+2)*132 + lrow] = av.z; As[(lk+3)*132 + lrow] = av.w;
        Bs[(lk+0)*132 + lrow] = bv.x; Bs[(lk+1)*132 + lrow] = bv.y;
        Bs[(lk+2)*132 + lrow] = bv.z; Bs[(lk+3)*132 + lrow] = bv.w;
        __syncthreads();
        #pragma unroll
        for (int kk = 0; kk < 8; kk++) {
            float a[8], b[8];
            *(float4*)(a)   = *(const float4*)(As + kk*132 + m0);
            *(float4*)(a+4) = *(const float4*)(As + kk*132 + m0 + 4);
            *(float4*)(b)   = *(const float4*)(Bs + kk*132 + n0);
            *(float4*)(b+4) = *(const float4*)(Bs + kk*132 + n0 + 4);
            #pragma unroll
            for (int i = 0; i < 8; i++)
                #pragma unroll
                for (int j = 0; j < 8; j++)
                    acc[i][j] = fmaf(a[i], b[j], acc[i][j]);
        }
        __syncthreads();
    }

    if (oBase == 0) {
        // gate logits: out_g[p][O]
        if (out_g != nullptr) {
            #pragma unroll
            for (int i = 0; i < 8; i++) {
                int p = pBase + m0 + i;
                float4 v0 = make_float4(acc[i][0], acc[i][1], acc[i][2], acc[i][3]);
                float4 v1 = make_float4(acc[i][4], acc[i][5], acc[i][6], acc[i][7]);
                *(float4*)(out_g + (size_t)p*128 + n0)     = v0;
                *(float4*)(out_g + (size_t)p*128 + n0 + 4) = v1;
            }
        }
        return;
    }

    // ab pair path: stage into smem val tile [64 t_local][128 pixels]
    int tBase = (oBase - 128) >> 1;           // 0,64,128,192
    const float msc = 0.0441941738241592f;    // 512^-0.5
    #pragma unroll
    for (int i = 0; i < 8; i++) {
        int p = pBase + m0 + i;
        float mv = mask[p] * msc;
        #pragma unroll
        for (int j = 0; j < 8; j += 2) {
            int tl = (n0 + j) >> 1;           // 0..63
            int t  = tBase + tl;
            float vp = acc[i][j]   + b_ab_p[t];
            float vg = acc[i][j+1] + b_ab_g[t];
            float val = vp * mv * (1.0f / (1.0f + __expf(-vg)));
            sh[tl*132 + (m0 + i)] = val;
        }
    }
    __syncthreads();
    float* dstM = (tBase < 128) ? g_a : g_b;
    int c = (tid & 31) * 4;
    int rb = tid >> 5;
    #pragma unroll
    for (int pass = 0; pass < 8; pass++) {
        int r = pass * 8 + rb;                // 0..63
        int h = (tBase + r) & 127;
        *(float4*)(dstM + (size_t)h*NP + pBase + c) = *(const float4*)(sh + r*132 + c);
    }
}

// ---------------------------------------------------------------------------
// Kernel C: triangle batched GEMM. For head h: X_h = A_h * B_h^T, all 512x512x512.
// grid (jTiles=4, iTiles=4, h=128); block 256 threads; 128x128 tile, BK=8.
// ---------------------------------------------------------------------------
__global__ __launch_bounds__(256)
void tri_kernel() {
    __shared__ float As[8*132];
    __shared__ float Bs[8*132];
    int h  = blockIdx.z;
    int i0 = blockIdx.y * 128;
    int j0 = blockIdx.x * 128;
    const float* A = g_a + (size_t)h * NP;
    const float* B = g_b + (size_t)h * NP;
    int tid = threadIdx.x;
    int lrow = tid >> 1;
    int lk   = (tid & 1) * 4;
    const float* arow = A + (i0 + lrow) * NN;
    const float* brow = B + (j0 + lrow) * NN;

    float acc[8][8];
    #pragma unroll
    for (int i = 0; i < 8; i++)
        #pragma unroll
        for (int j = 0; j < 8; j++) acc[i][j] = 0.f;

    int m0 = (tid >> 4) * 8;
    int n0 = (tid & 15) * 8;

    for (int k0 = 0; k0 < NN; k0 += 8) {
        float4 av = *(const float4*)(arow + k0 + lk);
        float4 bv = *(const float4*)(brow + k0 + lk);
        As[(lk+0)*132 + lrow] = av.x; As[(lk+1)*132 + lrow] = av.y;
        As[(lk+2)*132 + lrow] = av.z; As[(lk+3)*132 + lrow] = av.w;
        Bs[(lk+0)*132 + lrow] = bv.x; Bs[(lk+1)*132 + lrow] = bv.y;
        Bs[(lk+2)*132 + lrow] = bv.z; Bs[(lk+3)*132 + lrow] = bv.w;
        __syncthreads();
        #pragma unroll
        for (int kk = 0; kk < 8; kk++) {
            float a[8], b[8];
            *(float4*)(a)   = *(const float4*)(As + kk*132 + m0);
            *(float4*)(a+4) = *(const float4*)(As + kk*132 + m0 + 4);
            *(float4*)(b)   = *(const float4*)(Bs + kk*132 + n0);
            *(float4*)(b+4) = *(const float4*)(Bs + kk*132 + n0 + 4);
            #pragma unroll
            for (int i = 0; i < 8; i++)
                #pragma unroll
                for (int j = 0; j < 8; j++)
                    acc[i][j] = fmaf(a[i], b[j], acc[i][j]);
        }
        __syncthreads();
    }
    float* crow = g_x + (size_t)h * NP;
    #pragma unroll
    for (int i = 0; i < 8; i++) {
        float* dst = crow + (size_t)(i0 + m0 + i) * NN + j0 + n0;
        *(float4*)(dst)     = make_float4(acc[i][0], acc[i][1], acc[i][2], acc[i][3]);
        *(float4*)(dst + 4) = make_float4(acc[i][4], acc[i][5], acc[i][6], acc[i][7]);
    }
}

// ---------------------------------------------------------------------------
// Kernel D: output LN over H + projection by w_z[d,h]. 64 pixels/block.
// ---------------------------------------------------------------------------
__global__ __launch_bounds__(256)
void out_kernel(const float* __restrict__ lnw,
                const float* __restrict__ lnb,
                const float* __restrict__ w_z,
                float* __restrict__ out_x) {
    __shared__ float xt[64*132];      // [pixel][h]
    __shared__ float ws[8*132];       // [kk][d]
    int tid = threadIdx.x;
    int p0 = blockIdx.x * 64;

    // gather x tile from head-major g_x (transpose on the fly)
    int c  = tid & 63;
    int hh = tid >> 6;                // 0..3
    for (int hb = 0; hb < 128; hb += 4) {
        int h = hb + hh;
        xt[c*132 + h] = g_x[(size_t)h*NP + p0 + c];
    }
    __syncthreads();

    // LN over h: 8 warps x 8 pixels each
    int warp = tid >> 5, lane = tid & 31;
    float4 wv = ((const float4*)lnw)[lane];
    float4 bv = ((const float4*)lnb)[lane];
    for (int pp = 0; pp < 8; pp++) {
        int p = warp * 8 + pp;
        float4 v = *(float4*)(xt + p*132 + lane*4);
        float s  = v.x + v.y + v.z + v.w;
        float sq = v.x*v.x + v.y*v.y + v.z*v.z + v.w*v.w;
        #pragma unroll
        for (int o = 16; o > 0; o >>= 1) {
            s  += __shfl_xor_sync(0xffffffffu, s,  o);
            sq += __shfl_xor_sync(0xffffffffu, sq, o);
        }
        float mean = s * (1.0f/128.0f);
        float var  = sq * (1.0f/128.0f) - mean*mean;
        float rs   = rsqrtf(var + 1e-5f);
        float4 o4;
        o4.x = (v.x-mean)*rs*wv.x + bv.x;
        o4.y = (v.y-mean)*rs*wv.y + bv.y;
        o4.z = (v.z-mean)*rs*wv.z + bv.z;
        o4.w = (v.w-mean)*rs*wv.w + bv.w;
        *(float4*)(xt + p*132 + lane*4) = o4;
    }
    __syncthreads();

    // GEMM: out[p,d] = sum_h xn[p,h] * w_z[d,h]   (64x128x128)
    float acc[4][8];
    #pragma unroll
    for (int i = 0; i < 4; i++)
        #pragma unroll
        for (int j = 0; j < 8; j++) acc[i][j] = 0.f;
    int m0 = (tid >> 4) * 4;
    int n0 = (tid & 15) * 8;
    int ld = tid >> 1;
    int lk = (tid & 1) * 4;
    for (int k0 = 0; k0 < 128; k0 += 8) {
        float4 w4 = *(const float4*)(w_z + ld*128 + k0 + lk);
        ws[(lk+0)*132 + ld] = w4.x; ws[(lk+1)*132 + ld] = w4.y;
        ws[(lk+2)*132 + ld] = w4.z; ws[(lk+3)*132 + ld] = w4.w;
        __syncthreads();
        #pragma unroll
        for (int kk = 0; kk < 8; kk++) {
            float a[4], b[8];
            #pragma unroll
            for (int i = 0; i < 4; i++) a[i] = xt[(m0+i)*132 + k0 + kk];
            *(float4*)(b)   = *(const float4*)(ws + kk*132 + n0);
            *(float4*)(b+4) = *(const float4*)(ws + kk*132 + n0 + 4);
            #pragma unroll
            for (int i = 0; i < 4; i++)
                #pragma unroll
                for (int j = 0; j < 8; j++)
                    acc[i][j] = fmaf(a[i], b[j], acc[i][j]);
        }
        __syncthreads();
    }
    #pragma unroll
    for (int i = 0; i < 4; i++) {
        float* dst = out_x + (size_t)(p0 + m0 + i)*128 + n0;
        *(float4*)(dst)     = make_float4(acc[i][0], acc[i][1], acc[i][2], acc[i][3]);
        *(float4*)(dst + 4) = make_float4(acc[i][4], acc[i][5], acc[i][6], acc[i][7]);
    }
}

// ---------------------------------------------------------------------------
extern "C" void kernel_launch(void* const* d_in, const int* in_sizes, int n_in,
                              void* d_out, int out_size) {
    const float* z       = (const float*)d_in[0];
    const float* mask    = (const float*)d_in[1];
    const float* ln_in_w = (const float*)d_in[2];
    const float* ln_in_b = (const float*)d_in[3];
    const float* w_ab_p  = (const float*)d_in[4];
    const float* b_ab_p  = (const float*)d_in[5];
    const float* w_ab_g  = (const float*)d_in[6];
    const float* b_ab_g  = (const float*)d_in[7];
    const float* w_g     = (const float*)d_in[8];
    const float* ln_out_w= (const float*)d_in[9];
    const float* ln_out_b= (const float*)d_in[10];
    const float* w_z     = (const float*)d_in[11];

    float* out_x = (float*)d_out;
    float* out_g = (out_size >= 2*NP*DD) ? (out_x + (size_t)NP*DD) : nullptr;

    ln_in_kernel<<<NP/8, 256>>>(z, ln_in_w, ln_in_b);
    proj_kernel<<<dim3(NP/128, 5), 256>>>(mask, w_ab_p, b_ab_p, w_ab_g, b_ab_g, w_g, out_g);
    tri_kernel<<<dim3(4, 4, 128), 256>>>();
    out_kernel<<<NP/64, 256>>>(ln_out_w, ln_out_b, w_z, out_x);
}

// round 2
// speedup vs baseline: 1.0029x; 1.0029x over previous
#include <cuda_runtime.h>
#include <math.h>

#define NN 512
#define DD 128
#define NP (NN*NN)        // 262144 pixels
// scratch (static __device__ per harness rules)
__device__ float g_zl[(size_t)NP*DD];   // layernormed input, pixel-major [p][d]
__device__ float g_a [(size_t)DD*NP];   // a, head-major [h][i*N+k]
__device__ float g_b [(size_t)DD*NP];   // b, head-major [h][j*N+k]
__device__ float g_x [(size_t)DD*NP];   // triangle result, head-major [h][i*N+j]

// ---------------------------------------------------------------------------
// Kernel A: input LayerNorm over D=128. One warp per pixel.
// ---------------------------------------------------------------------------
__global__ void ln_in_kernel(const float* __restrict__ z,
                             const float* __restrict__ lnw,
                             const float* __restrict__ lnb) {
    int warp = threadIdx.x >> 5;
    int lane = threadIdx.x & 31;
    int p = blockIdx.x * 8 + warp;
    const float4* zin = (const float4*)(z + (size_t)p * DD);
    float4 v = zin[lane];
    float s  = v.x + v.y + v.z + v.w;
    float sq = v.x*v.x + v.y*v.y + v.z*v.z + v.w*v.w;
    #pragma unroll
    for (int o = 16; o > 0; o >>= 1) {
        s  += __shfl_xor_sync(0xffffffffu, s,  o);
        sq += __shfl_xor_sync(0xffffffffu, sq, o);
    }
    float mean = s * (1.0f/128.0f);
    float var  = sq * (1.0f/128.0f) - mean*mean;
    float rs   = rsqrtf(var + 1e-5f);
    float4 wv = ((const float4*)lnw)[lane];
    float4 bv = ((const float4*)lnb)[lane];
    float4 o4;
    o4.x = (v.x-mean)*rs*wv.x + bv.x;
    o4.y = (v.y-mean)*rs*wv.y + bv.y;
    o4.z = (v.z-mean)*rs*wv.z + bv.z;
    o4.w = (v.w-mean)*rs*wv.w + bv.w;
    ((float4*)(g_zl + (size_t)p*DD))[lane] = o4;
}

// ---------------------------------------------------------------------------
// Kernel B: projection GEMM  C[p,O] = zl[p,:] . Wrow(O)  with fused epilogue.
// Virtual weight matrix rows O: 0..127 = w_g; 128+2t = w_ab_p[t]; 129+2t = w_ab_g[t].
// Block tile 128 pixels x 128 outputs, K=128, BK=8, 256 threads, 8x8/thread.
// Epilogue: by==0 -> gate logits g (straight to d_out).
//           by>0  -> pairs (p,g): val=(p+bp)*m*sigmoid(g+bg); staged through
//                    smem then written coalesced, head-major, into g_a / g_b.
// ---------------------------------------------------------------------------
__global__ __launch_bounds__(256)
void proj_kernel(const float* __restrict__ mask,
                 const float* __restrict__ w_ab_p, const float* __restrict__ b_ab_p,
                 const float* __restrict__ w_ab_g, const float* __restrict__ b_ab_g,
                 const float* __restrict__ w_g,
                 float* __restrict__ out_g) {
    __shared__ float sh[64*132];              // overlaid: As(8x132) + Bs(8x132) | val(64x132)
    float* As = sh;                           // [8][132]
    float* Bs = sh + 8*132;                   // [8][132]

    int tid = threadIdx.x;
    int pBase = blockIdx.x * 128;
    int oBase = blockIdx.y * 128;

    int lrow = tid >> 1;
    int lk   = (tid & 1) * 4;
    const float* arow = g_zl + (size_t)(pBase + lrow) * DD;
    const float* wrow;
    {
        int O = oBase + lrow;
        if (O < 128) wrow = w_g + O * DD;
        else {
            int t = (O - 128) >> 1;
            wrow = ((O - 128) & 1) ? (w_ab_g + t * DD) : (w_ab_p + t * DD);
        }
    }

    float acc[8][8];
    #pragma unroll
    for (int i = 0; i < 8; i++)
        #pragma unroll
        for (int j = 0; j < 8; j++) acc[i][j] = 0.f;

    int m0 = (tid >> 4) * 8;
    int n0 = (tid & 15) * 8;

    for (int k0 = 0; k0 < DD; k0 += 8) {
        float4 av = *(const float4*)(arow + k0 + lk);
        float4 bv = *(const float4*)(wrow + k0 + lk);
        As[(lk+0)*132 + lrow] = av.x; As[(lk+1)*132 + lrow] = av.y;
        As[(lk+2)*132 + lrow] = av.z; As[(lk+3)*132 + lrow] = av.w;
        Bs[(lk+0)*132 + lrow] = bv.x; Bs[(lk+1)*132 + lrow] = bv.y;
        Bs[(lk+2)*132 + lrow] = bv.z; Bs[(lk+3)*132 + lrow] = bv.w;
        __syncthreads();
        #pragma unroll
        for (int kk = 0; kk < 8; kk++) {
            float a[8], b[8];
            *(float4*)(a)   = *(const float4*)(As + kk*132 + m0);
            *(float4*)(a+4) = *(const float4*)(As + kk*132 + m0 + 4);
            *(float4*)(b)   = *(const float4*)(Bs + kk*132 + n0);
            *(float4*)(b+4) = *(const float4*)(Bs + kk*132 + n0 + 4);
            #pragma unroll
            for (int i = 0; i < 8; i++)
                #pragma unroll
                for (int j = 0; j < 8; j++)
                    acc[i][j] = fmaf(a[i], b[j], acc[i][j]);
        }
        __syncthreads();
    }

    if (oBase == 0) {
        // gate logits: out_g[p][O]
        if (out_g != nullptr) {
            #pragma unroll
            for (int i = 0; i < 8; i++) {
                int p = pBase + m0 + i;
                float4 v0 = make_float4(acc[i][0], acc[i][1], acc[i][2], acc[i][3]);
                float4 v1 = make_float4(acc[i][4], acc[i][5], acc[i][6], acc[i][7]);
                *(float4*)(out_g + (size_t)p*128 + n0)     = v0;
                *(float4*)(out_g + (size_t)p*128 + n0 + 4) = v1;
            }
        }
        return;
    }

    // ab pair path: stage into smem val tile [64 t_local][128 pixels]
    int tBase = (oBase - 128) >> 1;           // 0,64,128,192
    const float msc = 0.0441941738241592f;    // 512^-0.5
    #pragma unroll
    for (int i = 0; i < 8; i++) {
        int p = pBase + m0 + i;
        float mv = mask[p] * msc;
        #pragma unroll
        for (int j = 0; j < 8; j += 2) {
            int tl = (n0 + j) >> 1;           // 0..63
            int t  = tBase + tl;
            float vp = acc[i][j]   + b_ab_p[t];
            float vg = acc[i][j+1] + b_ab_g[t];
            float val = vp * mv * (1.0f / (1.0f + __expf(-vg)));
            sh[tl*132 + (m0 + i)] = val;
        }
    }
    __syncthreads();
    float* dstM = (tBase < 128) ? g_a : g_b;
    int c = (tid & 31) * 4;
    int rb = tid >> 5;
    #pragma unroll
    for (int pass = 0; pass < 8; pass++) {
        int r = pass * 8 + rb;                // 0..63
        int h = (tBase + r) & 127;
        *(float4*)(dstM + (size_t)h*NP + pBase + c) = *(const float4*)(sh + r*132 + c);
    }
}

// ---------------------------------------------------------------------------
// Kernel C: triangle batched GEMM. For head h: X_h = A_h * B_h^T, all 512x512x512.
// grid (jTiles=4, iTiles=4, h=128); block 256 threads; 128x128 tile, BK=8.
// ---------------------------------------------------------------------------
__global__ __launch_bounds__(256)
void tri_kernel() {
    __shared__ float As[8*132];
    __shared__ float Bs[8*132];
    int h  = blockIdx.z;
    int i0 = blockIdx.y * 128;
    int j0 = blockIdx.x * 128;
    const float* A = g_a + (size_t)h * NP;
    const float* B = g_b + (size_t)h * NP;
    int tid = threadIdx.x;
    int lrow = tid >> 1;
    int lk   = (tid & 1) * 4;
    const float* arow = A + (i0 + lrow) * NN;
    const float* brow = B + (j0 + lrow) * NN;

    float acc[8][8];
    #pragma unroll
    for (int i = 0; i < 8; i++)
        #pragma unroll
        for (int j = 0; j < 8; j++) acc[i][j] = 0.f;

    int m0 = (tid >> 4) * 8;
    int n0 = (tid & 15) * 8;

    for (int k0 = 0; k0 < NN; k0 += 8) {
        float4 av = *(const float4*)(arow + k0 + lk);
        float4 bv = *(const float4*)(brow + k0 + lk);
        As[(lk+0)*132 + lrow] = av.x; As[(lk+1)*132 + lrow] = av.y;
        As[(lk+2)*132 + lrow] = av.z; As[(lk+3)*132 + lrow] = av.w;
        Bs[(lk+0)*132 + lrow] = bv.x; Bs[(lk+1)*132 + lrow] = bv.y;
        Bs[(lk+2)*132 + lrow] = bv.z; Bs[(lk+3)*132 + lrow] = bv.w;
        __syncthreads();
        #pragma unroll
        for (int kk = 0; kk < 8; kk++) {
            float a[8], b[8];
            *(float4*)(a)   = *(const float4*)(As + kk*132 + m0);
            *(float4*)(a+4) = *(const float4*)(As + kk*132 + m0 + 4);
            *(float4*)(b)   = *(const float4*)(Bs + kk*132 + n0);
            *(float4*)(b+4) = *(const float4*)(Bs + kk*132 + n0 + 4);
            #pragma unroll
            for (int i = 0; i < 8; i++)
                #pragma unroll
                for (int j = 0; j < 8; j++)
                    acc[i][j] = fmaf(a[i], b[j], acc[i][j]);
        }
        __syncthreads();
    }
    float* crow = g_x + (size_t)h * NP;
    #pragma unroll
    for (int i = 0; i < 8; i++) {
        float* dst = crow + (size_t)(i0 + m0 + i) * NN + j0 + n0;
        *(float4*)(dst)     = make_float4(acc[i][0], acc[i][1], acc[i][2], acc[i][3]);
        *(float4*)(dst + 4) = make_float4(acc[i][4], acc[i][5], acc[i][6], acc[i][7]);
    }
}

// ---------------------------------------------------------------------------
// Kernel D: output LN over H + projection by w_z[d,h]. 64 pixels/block.
// ---------------------------------------------------------------------------
__global__ __launch_bounds__(256)
void out_kernel(const float* __restrict__ lnw,
                const float* __restrict__ lnb,
                const float* __restrict__ w_z,
                float* __restrict__ out_x) {
    __shared__ float xt[64*132];      // [pixel][h]
    __shared__ float ws[8*132];       // [kk][d]
    int tid = threadIdx.x;
    int p0 = blockIdx.x * 64;

    // gather x tile from head-major g_x (transpose on the fly)
    int c  = tid & 63;
    int hh = tid >> 6;                // 0..3
    for (int hb = 0; hb < 128; hb += 4) {
        int h = hb + hh;
        xt[c*132 + h] = g_x[(size_t)h*NP + p0 + c];
    }
    __syncthreads();

    // LN over h: 8 warps x 8 pixels each
    int warp = tid >> 5, lane = tid & 31;
    float4 wv = ((const float4*)lnw)[lane];
    float4 bv = ((const float4*)lnb)[lane];
    for (int pp = 0; pp < 8; pp++) {
        int p = warp * 8 + pp;
        float4 v = *(float4*)(xt + p*132 + lane*4);
        float s  = v.x + v.y + v.z + v.w;
        float sq = v.x*v.x + v.y*v.y + v.z*v.z + v.w*v.w;
        #pragma unroll
        for (int o = 16; o > 0; o >>= 1) {
            s  += __shfl_xor_sync(0xffffffffu, s,  o);
            sq += __shfl_xor_sync(0xffffffffu, sq, o);
        }
        float mean = s * (1.0f/128.0f);
        float var  = sq * (1.0f/128.0f) - mean*mean;
        float rs   = rsqrtf(var + 1e-5f);
        float4 o4;
        o4.x = (v.x-mean)*rs*wv.x + bv.x;
        o4.y = (v.y-mean)*rs*wv.y + bv.y;
        o4.z = (v.z-mean)*rs*wv.z + bv.z;
        o4.w = (v.w-mean)*rs*wv.w + bv.w;
        *(float4*)(xt + p*132 + lane*4) = o4;
    }
    __syncthreads();

    // GEMM: out[p,d] = sum_h xn[p,h] * w_z[d,h]   (64x128x128)
    float acc[4][8];
    #pragma unroll
    for (int i = 0; i < 4; i++)
        #pragma unroll
        for (int j = 0; j < 8; j++) acc[i][j] = 0.f;
    int m0 = (tid >> 4) * 4;
    int n0 = (tid & 15) * 8;
    int ld = tid >> 1;
    int lk = (tid & 1) * 4;
    for (int k0 = 0; k0 < 128; k0 += 8) {
        float4 w4 = *(const float4*)(w_z + ld*128 + k0 + lk);
        ws[(lk+0)*132 + ld] = w4.x; ws[(lk+1)*132 + ld] = w4.y;
        ws[(lk+2)*132 + ld] = w4.z; ws[(lk+3)*132 + ld] = w4.w;
        __syncthreads();
        #pragma unroll
        for (int kk = 0; kk < 8; kk++) {
            float a[4], b[8];
            #pragma unroll
            for (int i = 0; i < 4; i++) a[i] = xt[(m0+i)*132 + k0 + kk];
            *(float4*)(b)   = *(const float4*)(ws + kk*132 + n0);
            *(float4*)(b+4) = *(const float4*)(ws + kk*132 + n0 + 4);
            #pragma unroll
            for (int i = 0; i < 4; i++)
                #pragma unroll
                for (int j = 0; j < 8; j++)
                    acc[i][j] = fmaf(a[i], b[j], acc[i][j]);
        }
        __syncthreads();
    }
    #pragma unroll
    for (int i = 0; i < 4; i++) {
        float* dst = out_x + (size_t)(p0 + m0 + i)*128 + n0;
        *(float4*)(dst)     = make_float4(acc[i][0], acc[i][1], acc[i][2], acc[i][3]);
        *(float4*)(dst + 4) = make_float4(acc[i][4], acc[i][5], acc[i][6], acc[i][7]);
    }
}

// ---------------------------------------------------------------------------
extern "C" void kernel_launch(void* const* d_in, const int* in_sizes, int n_in,
                              void* d_out, int out_size) {
    const float* z       = (const float*)d_in[0];
    const float* mask    = (const float*)d_in[1];
    const float* ln_in_w = (const float*)d_in[2];
    const float* ln_in_b = (const float*)d_in[3];
    const float* w_ab_p  = (const float*)d_in[4];
    const float* b_ab_p  = (const float*)d_in[5];
    const float* w_ab_g  = (const float*)d_in[6];
    const float* b_ab_g  = (const float*)d_in[7];
    const float* w_g     = (const float*)d_in[8];
    const float* ln_out_w= (const float*)d_in[9];
    const float* ln_out_b= (const float*)d_in[10];
    const float* w_z     = (const float*)d_in[11];

    float* out_x = (float*)d_out;
    float* out_g = (out_size >= 2*NP*DD) ? (out_x + (size_t)NP*DD) : nullptr;

    ln_in_kernel<<<NP/8, 256>>>(z, ln_in_w, ln_in_b);
    proj_kernel<<<dim3(NP/128, 5), 256>>>(mask, w_ab_p, b_ab_p, w_ab_g, b_ab_g, w_g, out_g);
    tri_kernel<<<dim3(4, 4, 128), 256>>>();
    out_kernel<<<NP/64, 256>>>(ln_out_w, ln_out_b, w_z, out_x);
}

// round 4
// speedup vs baseline: 2.3689x; 2.3619x over previous
#include <cuda_runtime.h>
#include <cstdint>
#include <math.h>

#define NN 512
#define DD 128
#define NP (NN*NN)

__device__ float g_zl[(size_t)NP*DD];   // layernormed input, pixel-major [p][d]
__device__ float g_a [(size_t)DD*NP];   // a, head-major [h][i*N+k]
__device__ float g_b [(size_t)DD*NP];   // b, head-major [h][j*N+k]
__device__ float g_x [(size_t)DD*NP];   // triangle result, head-major [h][i*N+j]

// ---------------------------------------------------------------------------
__device__ __forceinline__ float tf32f(float f){
    uint32_t u; asm("cvt.rna.tf32.f32 %0, %1;" : "=r"(u) : "f"(f));
    return __uint_as_float(u);
}
__device__ __forceinline__ void mma8(float c[4], uint32_t a0, uint32_t a1,
                                     uint32_t a2, uint32_t a3,
                                     uint32_t b0, uint32_t b1){
    asm volatile(
        "mma.sync.aligned.m16n8k8.row.col.f32.tf32.tf32.f32 "
        "{%0,%1,%2,%3}, {%4,%5,%6,%7}, {%8,%9}, {%0,%1,%2,%3};"
        : "+f"(c[0]), "+f"(c[1]), "+f"(c[2]), "+f"(c[3])
        : "r"(a0), "r"(a1), "r"(a2), "r"(a3), "r"(b0), "r"(b1));
}

// ---------------------------------------------------------------------------
// Kernel A: input LayerNorm over D=128. One warp per pixel.
// ---------------------------------------------------------------------------
__global__ void ln_in_kernel(const float* __restrict__ z,
                             const float* __restrict__ lnw,
                             const float* __restrict__ lnb) {
    int warp = threadIdx.x >> 5;
    int lane = threadIdx.x & 31;
    int p = blockIdx.x * 8 + warp;
    const float4* zin = (const float4*)(z + (size_t)p * DD);
    float4 v = zin[lane];
    float s  = v.x + v.y + v.z + v.w;
    float sq = v.x*v.x + v.y*v.y + v.z*v.z + v.w*v.w;
    #pragma unroll
    for (int o = 16; o > 0; o >>= 1) {
        s  += __shfl_xor_sync(0xffffffffu, s,  o);
        sq += __shfl_xor_sync(0xffffffffu, sq, o);
    }
    float mean = s * (1.0f/128.0f);
    float var  = sq * (1.0f/128.0f) - mean*mean;
    float rs   = rsqrtf(var + 1e-5f);
    float4 wv = ((const float4*)lnw)[lane];
    float4 bv = ((const float4*)lnb)[lane];
    float4 o4;
    o4.x = (v.x-mean)*rs*wv.x + bv.x;
    o4.y = (v.y-mean)*rs*wv.y + bv.y;
    o4.z = (v.z-mean)*rs*wv.z + bv.z;
    o4.w = (v.w-mean)*rs*wv.w + bv.w;
    ((float4*)(g_zl + (size_t)p*DD))[lane] = o4;
}

// ---------------------------------------------------------------------------
// Kernel B: projection GEMM (tf32 mma). C[p,O] = zl[p,:]·Wrow(O).
// Virtual rows: oBase==0 -> w_g; else even=w_ab_p, odd=w_ab_g (interleaved).
// Block 128px x 128O, K=128 in 4 chunks of 32. Warps 2x4, each 64x32.
// ---------------------------------------------------------------------------
__global__ __launch_bounds__(256)
void proj_kernel(const float* __restrict__ mask,
                 const float* __restrict__ w_ab_p, const float* __restrict__ b_ab_p,
                 const float* __restrict__ w_ab_g, const float* __restrict__ b_ab_g,
                 const float* __restrict__ w_g,
                 float* __restrict__ out_g) {
    __shared__ float sh[2*128*36];
    float* As = sh;
    float* Ws = sh + 128*36;
    int tid = threadIdx.x, warp = tid >> 5, lane = tid & 31;
    int grp = lane >> 2, qid = lane & 3;
    int pBase = blockIdx.x * 128;
    int oBase = blockIdx.y * 128;
    int wm = warp >> 2, wn = warp & 3;
    int mB = wm*64, nB = wn*32;

    float c[4][4][4];
    #pragma unroll
    for (int a = 0; a < 4; a++)
        #pragma unroll
        for (int b = 0; b < 4; b++)
            #pragma unroll
            for (int d = 0; d < 4; d++) c[a][b][d] = 0.f;

    int r = tid >> 3, cc = (tid & 7) << 2;
    for (int kc = 0; kc < 4; kc++) {
        #pragma unroll
        for (int k = 0; k < 4; k++) {
            int rr = r + k*32;
            float4 va = *(const float4*)(g_zl + (size_t)(pBase+rr)*DD + kc*32 + cc);
            const float* wrow;
            if (oBase == 0) wrow = w_g + rr*DD;
            else {
                int O = oBase + rr;
                int t = (O - 128) >> 1;
                wrow = (O & 1) ? (w_ab_g + t*DD) : (w_ab_p + t*DD);
            }
            float4 vb = *(const float4*)(wrow + kc*32 + cc);
            float* pa = As + rr*36 + cc;
            pa[0]=tf32f(va.x); pa[1]=tf32f(va.y); pa[2]=tf32f(va.z); pa[3]=tf32f(va.w);
            float* pw = Ws + rr*36 + cc;
            pw[0]=tf32f(vb.x); pw[1]=tf32f(vb.y); pw[2]=tf32f(vb.z); pw[3]=tf32f(vb.w);
        }
        __syncthreads();
        #pragma unroll
        for (int ks = 0; ks < 4; ks++) {
            int k0 = ks*8;
            uint32_t bf[4][2];
            #pragma unroll
            for (int nt = 0; nt < 4; nt++) {
                int rowb = (nB + nt*8 + grp)*36 + k0 + qid;
                bf[nt][0] = __float_as_uint(Ws[rowb]);
                bf[nt][1] = __float_as_uint(Ws[rowb + 4]);
            }
            #pragma unroll
            for (int mt = 0; mt < 4; mt++) {
                int rowa = (mB + mt*16 + grp)*36 + k0 + qid;
                uint32_t a0 = __float_as_uint(As[rowa]);
                uint32_t a1 = __float_as_uint(As[rowa + 8*36]);
                uint32_t a2 = __float_as_uint(As[rowa + 4]);
                uint32_t a3 = __float_as_uint(As[rowa + 8*36 + 4]);
                #pragma unroll
                for (int nt = 0; nt < 4; nt++)
                    mma8(c[mt][nt], a0, a1, a2, a3, bf[nt][0], bf[nt][1]);
            }
        }
        __syncthreads();
    }

    if (oBase == 0) {
        if (out_g != nullptr) {
            #pragma unroll
            for (int mt = 0; mt < 4; mt++) {
                int p = pBase + mB + mt*16 + grp;
                #pragma unroll
                for (int nt = 0; nt < 4; nt++) {
                    int O = nB + nt*8 + 2*qid;
                    *(float2*)(out_g + (size_t)p*DD + O)     = make_float2(c[mt][nt][0], c[mt][nt][1]);
                    *(float2*)(out_g + (size_t)(p+8)*DD + O) = make_float2(c[mt][nt][2], c[mt][nt][3]);
                }
            }
        }
        return;
    }

    // ab path: thread cols (2q,2q+1) = (p-logit, g-logit) of head tl.
    int tB = (oBase - 128) >> 1;              // 0,64,128,192
    const float msc = 0.044194173824159216f;  // 512^-0.5
    float bp[4], bg[4];
    #pragma unroll
    for (int nt = 0; nt < 4; nt++) {
        int t = tB + wn*16 + nt*4 + qid;
        bp[nt] = b_ab_p[t];
        bg[nt] = b_ab_g[t];
    }
    float* stage = sh;                        // [64][132] overlay (post-sync)
    #pragma unroll
    for (int mt = 0; mt < 4; mt++) {
        int px = mB + mt*16 + grp;
        float mv0 = mask[pBase + px] * msc;
        float mv1 = mask[pBase + px + 8] * msc;
        #pragma unroll
        for (int nt = 0; nt < 4; nt++) {
            int tl = wn*16 + nt*4 + qid;
            float v0 = (c[mt][nt][0] + bp[nt]) * mv0 * (1.0f/(1.0f + __expf(-(c[mt][nt][1] + bg[nt]))));
            float v1 = (c[mt][nt][2] + bp[nt]) * mv1 * (1.0f/(1.0f + __expf(-(c[mt][nt][3] + bg[nt]))));
            stage[tl*132 + px]     = v0;
            stage[tl*132 + px + 8] = v1;
        }
    }
    __syncthreads();
    float* dstM = (tB < 128) ? g_a : g_b;
    int rowB = tB & 127;
    #pragma unroll
    for (int k = 0; k < 8; k++) {
        int idx = tid + k*256;
        int rr = idx >> 5, c4 = (idx & 31)*4;
        *(float4*)(dstM + (size_t)(rowB + rr)*NP + pBase + c4) = *(const float4*)(stage + rr*132 + c4);
    }
}

// ---------------------------------------------------------------------------
// Kernel C: triangle batched GEMM (tf32 mma). Head h: X_h = A_h·B_h^T.
// grid (16, 128); 128x128 tile; K=512 in 16 chunks of 32.
// ---------------------------------------------------------------------------
__global__ __launch_bounds__(256)
void tri_kernel() {
    __shared__ float As[128*36];
    __shared__ float Bs[128*36];
    int tid = threadIdx.x, warp = tid >> 5, lane = tid & 31;
    int grp = lane >> 2, qid = lane & 3;
    int h  = blockIdx.y;
    int i0 = (blockIdx.x >> 2) * 128;
    int j0 = (blockIdx.x & 3) * 128;
    const float* A = g_a + (size_t)h*NP + (size_t)i0*NN;
    const float* B = g_b + (size_t)h*NP + (size_t)j0*NN;
    int wm = warp >> 2, wn = warp & 3;
    int mB = wm*64, nB = wn*32;

    float c[4][4][4];
    #pragma unroll
    for (int a = 0; a < 4; a++)
        #pragma unroll
        for (int b = 0; b < 4; b++)
            #pragma unroll
            for (int d = 0; d < 4; d++) c[a][b][d] = 0.f;

    int r = tid >> 3, cc = (tid & 7) << 2;
    for (int kc = 0; kc < 16; kc++) {
        #pragma unroll
        for (int k = 0; k < 4; k++) {
            int rr = r + k*32;
            float4 va = *(const float4*)(A + (size_t)rr*NN + kc*32 + cc);
            float4 vb = *(const float4*)(B + (size_t)rr*NN + kc*32 + cc);
            float* pa = As + rr*36 + cc;
            pa[0]=tf32f(va.x); pa[1]=tf32f(va.y); pa[2]=tf32f(va.z); pa[3]=tf32f(va.w);
            float* pb = Bs + rr*36 + cc;
            pb[0]=tf32f(vb.x); pb[1]=tf32f(vb.y); pb[2]=tf32f(vb.z); pb[3]=tf32f(vb.w);
        }
        __syncthreads();
        #pragma unroll
        for (int ks = 0; ks < 4; ks++) {
            int k0 = ks*8;
            uint32_t bf[4][2];
            #pragma unroll
            for (int nt = 0; nt < 4; nt++) {
                int rowb = (nB + nt*8 + grp)*36 + k0 + qid;
                bf[nt][0] = __float_as_uint(Bs[rowb]);
                bf[nt][1] = __float_as_uint(Bs[rowb + 4]);
            }
            #pragma unroll
            for (int mt = 0; mt < 4; mt++) {
                int rowa = (mB + mt*16 + grp)*36 + k0 + qid;
                uint32_t a0 = __float_as_uint(As[rowa]);
                uint32_t a1 = __float_as_uint(As[rowa + 8*36]);
                uint32_t a2 = __float_as_uint(As[rowa + 4]);
                uint32_t a3 = __float_as_uint(As[rowa + 8*36 + 4]);
                #pragma unroll
                for (int nt = 0; nt < 4; nt++)
                    mma8(c[mt][nt], a0, a1, a2, a3, bf[nt][0], bf[nt][1]);
            }
        }
        __syncthreads();
    }
    float* X = g_x + (size_t)h*NP;
    #pragma unroll
    for (int mt = 0; mt < 4; mt++) {
        int row = i0 + mB + mt*16 + grp;
        #pragma unroll
        for (int nt = 0; nt < 4; nt++) {
            int col = j0 + nB + nt*8 + 2*qid;
            *(float2*)(X + (size_t)row*NN + col)     = make_float2(c[mt][nt][0], c[mt][nt][1]);
            *(float2*)(X + (size_t)(row+8)*NN + col) = make_float2(c[mt][nt][2], c[mt][nt][3]);
        }
    }
}

// ---------------------------------------------------------------------------
// Kernel D: gather-transpose + LN over H + GEMM vs w_z (tf32 mma).
// Block = 128 pixels x 128 d. smem: xt[128][132] + ws[128][36] (dynamic).
// ---------------------------------------------------------------------------
__global__ __launch_bounds__(256)
void out_kernel(const float* __restrict__ lnw,
                const float* __restrict__ lnb,
                const float* __restrict__ w_z,
                float* __restrict__ out_x) {
    extern __shared__ float xs[];
    float* xt = xs;                // [128 px][132]
    float* ws = xs + 128*132;      // [128 d][36] per chunk
    int tid = threadIdx.x, warp = tid >> 5, lane = tid & 31;
    int grp = lane >> 2, qid = lane & 3;
    int p0 = blockIdx.x * 128;

    // gather transpose from head-major g_x
    int cpx = tid & 127, hh0 = tid >> 7;
    for (int hb = 0; hb < 128; hb += 2) {
        int h_ = hb + hh0;
        xt[cpx*132 + h_] = g_x[(size_t)h_*NP + p0 + cpx];
    }
    __syncthreads();

    // LN over h: warp w -> pixels w*16..w*16+15 ; store tf32-rounded
    float4 wv  = ((const float4*)lnw)[lane];
    float4 bvv = ((const float4*)lnb)[lane];
    for (int pp = 0; pp < 16; pp++) {
        int p = warp*16 + pp;
        float4 v = *(float4*)(xt + p*132 + lane*4);
        float s  = v.x + v.y + v.z + v.w;
        float sq = v.x*v.x + v.y*v.y + v.z*v.z + v.w*v.w;
        #pragma unroll
        for (int o = 16; o > 0; o >>= 1) {
            s  += __shfl_xor_sync(0xffffffffu, s,  o);
            sq += __shfl_xor_sync(0xffffffffu, sq, o);
        }
        float mean = s * (1.0f/128.0f);
        float var  = sq * (1.0f/128.0f) - mean*mean;
        float rs   = rsqrtf(var + 1e-5f);
        float* d = xt + p*132 + lane*4;
        d[0] = tf32f((v.x-mean)*rs*wv.x + bvv.x);
        d[1] = tf32f((v.y-mean)*rs*wv.y + bvv.y);
        d[2] = tf32f((v.z-mean)*rs*wv.z + bvv.z);
        d[3] = tf32f((v.w-mean)*rs*wv.w + bvv.w);
    }
    __syncthreads();

    int wm = warp >> 2, wn = warp & 3;
    int mB = wm*64, nB = wn*32;
    float c[4][4][4];
    #pragma unroll
    for (int a = 0; a < 4; a++)
        #pragma unroll
        for (int b = 0; b < 4; b++)
            #pragma unroll
            for (int d = 0; d < 4; d++) c[a][b][d] = 0.f;

    int r = tid >> 3, cc = (tid & 7) << 2;
    for (int kc = 0; kc < 4; kc++) {
        #pragma unroll
        for (int k = 0; k < 4; k++) {
            int rr = r + k*32;
            float4 v = *(const float4*)(w_z + rr*DD + kc*32 + cc);
            float* pw = ws + rr*36 + cc;
            pw[0]=tf32f(v.x); pw[1]=tf32f(v.y); pw[2]=tf32f(v.z); pw[3]=tf32f(v.w);
        }
        __syncthreads();
        #pragma unroll
        for (int ks = 0; ks < 4; ks++) {
            int k0w = ks*8;
            int k0a = kc*32 + ks*8;
            uint32_t bf[4][2];
            #pragma unroll
            for (int nt = 0; nt < 4; nt++) {
                int rowb = (nB + nt*8 + grp)*36 + k0w + qid;
                bf[nt][0] = __float_as_uint(ws[rowb]);
                bf[nt][1] = __float_as_uint(ws[rowb + 4]);
            }
            #pragma unroll
            for (int mt = 0; mt < 4; mt++) {
                int rowa = (mB + mt*16 + grp)*132 + k0a + qid;
                uint32_t a0 = __float_as_uint(xt[rowa]);
                uint32_t a1 = __float_as_uint(xt[rowa + 8*132]);
                uint32_t a2 = __float_as_uint(xt[rowa + 4]);
                uint32_t a3 = __float_as_uint(xt[rowa + 8*132 + 4]);
                #pragma unroll
                for (int nt = 0; nt < 4; nt++)
                    mma8(c[mt][nt], a0, a1, a2, a3, bf[nt][0], bf[nt][1]);
            }
        }
        __syncthreads();
    }
    #pragma unroll
    for (int mt = 0; mt < 4; mt++) {
        int p = p0 + mB + mt*16 + grp;
        #pragma unroll
        for (int nt = 0; nt < 4; nt++) {
            int d = nB + nt*8 + 2*qid;
            *(float2*)(out_x + (size_t)p*DD + d)     = make_float2(c[mt][nt][0], c[mt][nt][1]);
            *(float2*)(out_x + (size_t)(p+8)*DD + d) = make_float2(c[mt][nt][2], c[mt][nt][3]);
        }
    }
}

// ---------------------------------------------------------------------------
extern "C" void kernel_launch(void* const* d_in, const int* in_sizes, int n_in,
                              void* d_out, int out_size) {
    const float* z       = (const float*)d_in[0];
    const float* mask    = (const float*)d_in[1];
    const float* ln_in_w = (const float*)d_in[2];
    const float* ln_in_b = (const float*)d_in[3];
    const float* w_ab_p  = (const float*)d_in[4];
    const float* b_ab_p  = (const float*)d_in[5];
    const float* w_ab_g  = (const float*)d_in[6];
    const float* b_ab_g  = (const float*)d_in[7];
    const float* w_g     = (const float*)d_in[8];
    const float* ln_out_w= (const float*)d_in[9];
    const float* ln_out_b= (const float*)d_in[10];
    const float* w_z     = (const float*)d_in[11];

    float* out_x = (float*)d_out;
    float* out_g = (out_size >= 2*NP*DD) ? (out_x + (size_t)NP*DD) : nullptr;

    const int outSmem = (128*132 + 128*36) * 4;  // 86016 B
    cudaFuncSetAttribute(out_kernel, cudaFuncAttributeMaxDynamicSharedMemorySize, outSmem);

    ln_in_kernel<<<NP/8, 256>>>(z, ln_in_w, ln_in_b);
    proj_kernel<<<dim3(NP/128, 5), 256>>>(mask, w_ab_p, b_ab_p, w_ab_g, b_ab_g, w_g, out_g);
    tri_kernel<<<dim3(16, 128), 256>>>();
    out_kernel<<<NP/128, 256, outSmem>>>(ln_out_w, ln_out_b, w_z, out_x);
}

// round 6
// speedup vs baseline: 2.7610x; 1.1655x over previous
#include <cuda_runtime.h>
#include <cstdint>
#include <math.h>

#define NN 512
#define DD 128
#define NP (NN*NN)

__device__ float g_zl[(size_t)NP*DD];   // LN'ed input, tf32-rounded, [p][d]
__device__ float g_a [(size_t)DD*NP];   // a, tf32-rounded, head-major [h][i*N+k]
__device__ float g_b [(size_t)DD*NP];   // b, tf32-rounded, head-major [h][j*N+k]
__device__ float g_x [(size_t)DD*NP];   // triangle result f32, head-major
__device__ float g_w [640*DD];          // virtual weight matrix, tf32-rounded

// ---------------------------------------------------------------------------
__device__ __forceinline__ float tf32f(float f){
    uint32_t u; asm("cvt.rna.tf32.f32 %0, %1;" : "=r"(u) : "f"(f));
    return __uint_as_float(u);
}
__device__ __forceinline__ void mma8(float c[4], uint32_t a0, uint32_t a1,
                                     uint32_t a2, uint32_t a3,
                                     uint32_t b0, uint32_t b1){
    asm volatile(
        "mma.sync.aligned.m16n8k8.row.col.f32.tf32.tf32.f32 "
        "{%0,%1,%2,%3}, {%4,%5,%6,%7}, {%8,%9}, {%0,%1,%2,%3};"
        : "+f"(c[0]), "+f"(c[1]), "+f"(c[2]), "+f"(c[3])
        : "r"(a0), "r"(a1), "r"(a2), "r"(a3), "r"(b0), "r"(b1));
}
__device__ __forceinline__ uint32_t smem_u32(const void* p){
    uint32_t a;
    asm("{ .reg .u64 t; cvta.to.shared.u64 t, %1; cvt.u32.u64 %0, t; }" : "=r"(a) : "l"(p));
    return a;
}
__device__ __forceinline__ void cp16(uint32_t dst, const float* src){
    asm volatile("cp.async.cg.shared.global [%0], [%1], 16;" :: "r"(dst), "l"(src) : "memory");
}
#define CP_COMMIT() asm volatile("cp.async.commit_group;" ::: "memory")
#define CP_WAIT0()  asm volatile("cp.async.wait_group 0;" ::: "memory")
#define CP_WAIT1()  asm volatile("cp.async.wait_group 1;" ::: "memory")

// ---------------------------------------------------------------------------
// prep_w: build tf32-rounded virtual weight matrix.
// rows 0..127 = w_g ; row 128+2t = w_ab_p[t] ; 129+2t = w_ab_g[t].
// ---------------------------------------------------------------------------
__global__ void prep_w(const float* __restrict__ wg,
                       const float* __restrict__ wap,
                       const float* __restrict__ wag){
    int idx = blockIdx.x*256 + threadIdx.x;      // 81920 total
    int row = idx >> 7, col = idx & 127;
    const float* src;
    if (row < 128) src = wg + row*DD;
    else { int t = (row-128)>>1; src = (row & 1) ? (wag + t*DD) : (wap + t*DD); }
    g_w[idx] = tf32f(src[col]);
}

// ---------------------------------------------------------------------------
// ln_in: LayerNorm over D=128, one warp per pixel; writes tf32-rounded.
// ---------------------------------------------------------------------------
__global__ void ln_in_kernel(const float* __restrict__ z,
                             const float* __restrict__ lnw,
                             const float* __restrict__ lnb) {
    int warp = threadIdx.x >> 5, lane = threadIdx.x & 31;
    int p = blockIdx.x * 8 + warp;
    float4 v = ((const float4*)(z + (size_t)p*DD))[lane];
    float s  = v.x + v.y + v.z + v.w;
    float sq = v.x*v.x + v.y*v.y + v.z*v.z + v.w*v.w;
    #pragma unroll
    for (int o = 16; o > 0; o >>= 1) {
        s  += __shfl_xor_sync(0xffffffffu, s,  o);
        sq += __shfl_xor_sync(0xffffffffu, sq, o);
    }
    float mean = s * (1.0f/128.0f);
    float var  = sq * (1.0f/128.0f) - mean*mean;
    float rs   = rsqrtf(var + 1e-5f);
    float4 wv = ((const float4*)lnw)[lane];
    float4 bv = ((const float4*)lnb)[lane];
    float4 o4;
    o4.x = tf32f((v.x-mean)*rs*wv.x + bv.x);
    o4.y = tf32f((v.y-mean)*rs*wv.y + bv.y);
    o4.z = tf32f((v.z-mean)*rs*wv.z + bv.z);
    o4.w = tf32f((v.w-mean)*rs*wv.w + bv.w);
    ((float4*)(g_zl + (size_t)p*DD))[lane] = o4;
}

// ---------------------------------------------------------------------------
// proj: one CTA per 128 pixels; A tile resident in smem; loops 5 W tiles of
// g_w with cp.async double-buffered K-chunk staging.
// smem: A [128][132] | W 2x[128][36] | stage [64][132]  = 138240 B
// ---------------------------------------------------------------------------
__global__ __launch_bounds__(256)
void proj_kernel(const float* __restrict__ mask,
                 const float* __restrict__ b_ab_p,
                 const float* __restrict__ b_ab_g,
                 float* __restrict__ out_g) {
    extern __shared__ float sh[];
    float* As    = sh;                    // stride 132
    float* Wb    = sh + 128*132;          // 2 x 128*36
    float* stage = Wb + 2*128*36;         // stride 132
    const int tid = threadIdx.x, warp = tid>>5, lane = tid&31;
    const int grp = lane>>2, qid = lane&3;
    const int wm = warp>>2, wn = warp&3;
    const int mB = wm*64, nB = wn*32;
    const int pBase = blockIdx.x*128;
    uint32_t sA = smem_u32(As), sW = smem_u32(Wb);

    // prefetch resident A tile: 128 rows x 128 floats = 4096 x 16B (FIXED)
    {
        const float* src = g_zl + (size_t)pBase*DD;
        #pragma unroll
        for (int t = 0; t < 16; t++){
            int idx = tid + t*256, r = idx >> 5, seg = idx & 31;
            cp16(sA + (uint32_t)(r*528 + seg*16), src + (size_t)r*DD + seg*4);
        }
        CP_COMMIT();
    }
    // prefetch W tile0 chunk0: 128 rows x 32 floats
    #pragma unroll
    for (int t = 0; t < 4; t++){
        int idx = tid + t*256, r = idx >> 3, seg = idx & 7;
        cp16(sW + (uint32_t)(r*144 + seg*16), g_w + (size_t)r*DD + seg*4);
    }
    CP_COMMIT();

    int buf = 0;
    for (int nt = 0; nt < 5; nt++) {
        float c[4][4][4];
        #pragma unroll
        for (int a = 0; a < 4; a++)
            #pragma unroll
            for (int b = 0; b < 4; b++)
                #pragma unroll
                for (int d = 0; d < 4; d++) c[a][b][d] = 0.f;

        for (int kc = 0; kc < 4; kc++) {
            int nn_ = nt, nk = kc + 1;
            if (nk == 4) { nn_ = nt + 1; nk = 0; }
            if (nn_ < 5) {
                uint32_t dst = sW + (uint32_t)((buf^1)*18432);
                const float* src = g_w + (size_t)nn_*128*DD + nk*32;
                #pragma unroll
                for (int t = 0; t < 4; t++){
                    int idx = tid + t*256, r = idx >> 3, seg = idx & 7;
                    cp16(dst + (uint32_t)(r*144 + seg*16), src + (size_t)r*DD + seg*4);
                }
                CP_COMMIT();
                CP_WAIT1();
            } else CP_WAIT0();
            __syncthreads();
            const float* Ws = Wb + buf*4608;
            #pragma unroll
            for (int ks = 0; ks < 4; ks++) {
                int k0w = ks*8, k0a = kc*32 + ks*8;
                uint32_t bf[4][2];
                #pragma unroll
                for (int n2 = 0; n2 < 4; n2++) {
                    int rowb = (nB + n2*8 + grp)*36 + k0w + qid;
                    bf[n2][0] = __float_as_uint(Ws[rowb]);
                    bf[n2][1] = __float_as_uint(Ws[rowb + 4]);
                }
                #pragma unroll
                for (int mt = 0; mt < 4; mt++) {
                    int rowa = (mB + mt*16 + grp)*132 + k0a + qid;
                    uint32_t a0 = __float_as_uint(As[rowa]);
                    uint32_t a1 = __float_as_uint(As[rowa + 8*132]);
                    uint32_t a2 = __float_as_uint(As[rowa + 4]);
                    uint32_t a3 = __float_as_uint(As[rowa + 8*132 + 4]);
                    #pragma unroll
                    for (int n2 = 0; n2 < 4; n2++)
                        mma8(c[mt][n2], a0, a1, a2, a3, bf[n2][0], bf[n2][1]);
                }
            }
            __syncthreads();
            buf ^= 1;
        }

        if (nt == 0) {
            if (out_g != nullptr) {
                #pragma unroll
                for (int mt = 0; mt < 4; mt++) {
                    int p = pBase + mB + mt*16 + grp;
                    #pragma unroll
                    for (int n2 = 0; n2 < 4; n2++) {
                        int O = nB + n2*8 + 2*qid;
                        *(float2*)(out_g + (size_t)p*DD + O)     = make_float2(c[mt][n2][0], c[mt][n2][1]);
                        *(float2*)(out_g + (size_t)(p+8)*DD + O) = make_float2(c[mt][n2][2], c[mt][n2][3]);
                    }
                }
            }
        } else {
            int tB = (nt-1)*64;
            const float msc = 0.044194173824159216f;
            float bp[4], bg[4];
            #pragma unroll
            for (int n2 = 0; n2 < 4; n2++) {
                int t = tB + wn*16 + n2*4 + qid;
                bp[n2] = b_ab_p[t];
                bg[n2] = b_ab_g[t];
            }
            #pragma unroll
            for (int mt = 0; mt < 4; mt++) {
                int px = mB + mt*16 + grp;
                float mv0 = mask[pBase + px] * msc;
                float mv1 = mask[pBase + px + 8] * msc;
                #pragma unroll
                for (int n2 = 0; n2 < 4; n2++) {
                    int tl = wn*16 + n2*4 + qid;
                    float v0 = tf32f((c[mt][n2][0] + bp[n2]) * mv0 *
                                     (1.0f/(1.0f + __expf(-(c[mt][n2][1] + bg[n2])))));
                    float v1 = tf32f((c[mt][n2][2] + bp[n2]) * mv1 *
                                     (1.0f/(1.0f + __expf(-(c[mt][n2][3] + bg[n2])))));
                    stage[tl*132 + px]     = v0;
                    stage[tl*132 + px + 8] = v1;
                }
            }
            __syncthreads();
            float* dstM = (tB < 128) ? g_a : g_b;
            int rowB = tB & 127;
            #pragma unroll
            for (int k = 0; k < 8; k++) {
                int idx = tid + k*256, rr = idx >> 5, c4 = (idx & 31)*4;
                *(float4*)(dstM + (size_t)(rowB + rr)*NP + pBase + c4) =
                    *(const float4*)(stage + rr*132 + c4);
            }
            __syncthreads();
        }
    }
}

// ---------------------------------------------------------------------------
// tri: head h: X_h = A_h · B_h^T (128x128 tile, K=512 in 16 chunks of 32),
// cp.async double-buffered A/B chunk staging (operands pre-rounded tf32).
// smem: 2 x (A[128][36] + B[128][36]) = 73728 B
// ---------------------------------------------------------------------------
__global__ __launch_bounds__(256)
void tri_kernel() {
    extern __shared__ float sh[];
    const int tid = threadIdx.x, warp = tid>>5, lane = tid&31;
    const int grp = lane>>2, qid = lane&3;
    const int wm = warp>>2, wn = warp&3;
    const int mB = wm*64, nB = wn*32;
    int h  = blockIdx.y;
    int i0 = (blockIdx.x >> 2) * 128;
    int j0 = (blockIdx.x & 3) * 128;
    const float* A = g_a + (size_t)h*NP + (size_t)i0*NN;
    const float* B = g_b + (size_t)h*NP + (size_t)j0*NN;
    uint32_t s0 = smem_u32(sh);

    // prefetch chunk 0
    #pragma unroll
    for (int t = 0; t < 4; t++){
        int idx = tid + t*256, r = idx >> 3, seg = idx & 7;
        cp16(s0 + (uint32_t)(r*144 + seg*16),         A + (size_t)r*NN + seg*4);
        cp16(s0 + (uint32_t)(18432 + r*144 + seg*16), B + (size_t)r*NN + seg*4);
    }
    CP_COMMIT();

    float c[4][4][4];
    #pragma unroll
    for (int a = 0; a < 4; a++)
        #pragma unroll
        for (int b = 0; b < 4; b++)
            #pragma unroll
            for (int d = 0; d < 4; d++) c[a][b][d] = 0.f;

    int buf = 0;
    for (int kc = 0; kc < 16; kc++) {
        if (kc + 1 < 16) {
            uint32_t dst = s0 + (uint32_t)((buf^1)*36864);
            const float* As_ = A + (kc+1)*32;
            const float* Bs_ = B + (kc+1)*32;
            #pragma unroll
            for (int t = 0; t < 4; t++){
                int idx = tid + t*256, r = idx >> 3, seg = idx & 7;
                cp16(dst + (uint32_t)(r*144 + seg*16),         As_ + (size_t)r*NN + seg*4);
                cp16(dst + (uint32_t)(18432 + r*144 + seg*16), Bs_ + (size_t)r*NN + seg*4);
            }
            CP_COMMIT();
            CP_WAIT1();
        } else CP_WAIT0();
        __syncthreads();
        const float* Asm = sh + buf*9216;
        const float* Bsm = Asm + 4608;
        #pragma unroll
        for (int ks = 0; ks < 4; ks++) {
            int k0 = ks*8;
            uint32_t bf[4][2];
            #pragma unroll
            for (int n2 = 0; n2 < 4; n2++) {
                int rowb = (nB + n2*8 + grp)*36 + k0 + qid;
                bf[n2][0] = __float_as_uint(Bsm[rowb]);
                bf[n2][1] = __float_as_uint(Bsm[rowb + 4]);
            }
            #pragma unroll
            for (int mt = 0; mt < 4; mt++) {
                int rowa = (mB + mt*16 + grp)*36 + k0 + qid;
                uint32_t a0 = __float_as_uint(Asm[rowa]);
                uint32_t a1 = __float_as_uint(Asm[rowa + 8*36]);
                uint32_t a2 = __float_as_uint(Asm[rowa + 4]);
                uint32_t a3 = __float_as_uint(Asm[rowa + 8*36 + 4]);
                #pragma unroll
                for (int n2 = 0; n2 < 4; n2++)
                    mma8(c[mt][n2], a0, a1, a2, a3, bf[n2][0], bf[n2][1]);
            }
        }
        __syncthreads();
        buf ^= 1;
    }
    float* X = g_x + (size_t)h*NP;
    #pragma unroll
    for (int mt = 0; mt < 4; mt++) {
        int row = i0 + mB + mt*16 + grp;
        #pragma unroll
        for (int n2 = 0; n2 < 4; n2++) {
            int col = j0 + nB + n2*8 + 2*qid;
            *(float2*)(X + (size_t)row*NN + col)     = make_float2(c[mt][n2][0], c[mt][n2][1]);
            *(float2*)(X + (size_t)(row+8)*NN + col) = make_float2(c[mt][n2][2], c[mt][n2][3]);
        }
    }
}

// ---------------------------------------------------------------------------
// out: gather-transpose + LN over H + GEMM vs w_z (tf32 mma).
// smem: xt[128][132] + ws[128][36]  = 86016 B
// ---------------------------------------------------------------------------
__global__ __launch_bounds__(256)
void out_kernel(const float* __restrict__ lnw,
                const float* __restrict__ lnb,
                const float* __restrict__ w_z,
                float* __restrict__ out_x) {
    extern __shared__ float xs[];
    float* xt = xs;                // [128 px][132]
    float* ws = xs + 128*132;      // [128 d][36] per chunk
    int tid = threadIdx.x, warp = tid >> 5, lane = tid & 31;
    int grp = lane >> 2, qid = lane & 3;
    int p0 = blockIdx.x * 128;

    int cpx = tid & 127, hh0 = tid >> 7;
    for (int hb = 0; hb < 128; hb += 2) {
        int h_ = hb + hh0;
        xt[cpx*132 + h_] = g_x[(size_t)h_*NP + p0 + cpx];
    }
    __syncthreads();

    float4 wv  = ((const float4*)lnw)[lane];
    float4 bvv = ((const float4*)lnb)[lane];
    for (int pp = 0; pp < 16; pp++) {
        int p = warp*16 + pp;
        float4 v = *(float4*)(xt + p*132 + lane*4);
        float s  = v.x + v.y + v.z + v.w;
        float sq = v.x*v.x + v.y*v.y + v.z*v.z + v.w*v.w;
        #pragma unroll
        for (int o = 16; o > 0; o >>= 1) {
            s  += __shfl_xor_sync(0xffffffffu, s,  o);
            sq += __shfl_xor_sync(0xffffffffu, sq, o);
        }
        float mean = s * (1.0f/128.0f);
        float var  = sq * (1.0f/128.0f) - mean*mean;
        float rs   = rsqrtf(var + 1e-5f);
        float* d = xt + p*132 + lane*4;
        d[0] = tf32f((v.x-mean)*rs*wv.x + bvv.x);
        d[1] = tf32f((v.y-mean)*rs*wv.y + bvv.y);
        d[2] = tf32f((v.z-mean)*rs*wv.z + bvv.z);
        d[3] = tf32f((v.w-mean)*rs*wv.w + bvv.w);
    }
    __syncthreads();

    int wm = warp >> 2, wn = warp & 3;
    int mB = wm*64, nB = wn*32;
    float c[4][4][4];
    #pragma unroll
    for (int a = 0; a < 4; a++)
        #pragma unroll
        for (int b = 0; b < 4; b++)
            #pragma unroll
            for (int d = 0; d < 4; d++) c[a][b][d] = 0.f;

    int r = tid >> 3, cc = (tid & 7) << 2;
    for (int kc = 0; kc < 4; kc++) {
        #pragma unroll
        for (int k = 0; k < 4; k++) {
            int rr = r + k*32;
            float4 v = *(const float4*)(w_z + rr*DD + kc*32 + cc);
            float* pw = ws + rr*36 + cc;
            pw[0]=tf32f(v.x); pw[1]=tf32f(v.y); pw[2]=tf32f(v.z); pw[3]=tf32f(v.w);
        }
        __syncthreads();
        #pragma unroll
        for (int ks = 0; ks < 4; ks++) {
            int k0w = ks*8;
            int k0a = kc*32 + ks*8;
            uint32_t bf[4][2];
            #pragma unroll
            for (int n2 = 0; n2 < 4; n2++) {
                int rowb = (nB + n2*8 + grp)*36 + k0w + qid;
                bf[n2][0] = __float_as_uint(ws[rowb]);
                bf[n2][1] = __float_as_uint(ws[rowb + 4]);
            }
            #pragma unroll
            for (int mt = 0; mt < 4; mt++) {
                int rowa = (mB + mt*16 + grp)*132 + k0a + qid;
                uint32_t a0 = __float_as_uint(xt[rowa]);
                uint32_t a1 = __float_as_uint(xt[rowa + 8*132]);
                uint32_t a2 = __float_as_uint(xt[rowa + 4]);
                uint32_t a3 = __float_as_uint(xt[rowa + 8*132 + 4]);
                #pragma unroll
                for (int n2 = 0; n2 < 4; n2++)
                    mma8(c[mt][n2], a0, a1, a2, a3, bf[n2][0], bf[n2][1]);
            }
        }
        __syncthreads();
    }
    #pragma unroll
    for (int mt = 0; mt < 4; mt++) {
        int p = p0 + mB + mt*16 + grp;
        #pragma unroll
        for (int n2 = 0; n2 < 4; n2++) {
            int d = nB + n2*8 + 2*qid;
            *(float2*)(out_x + (size_t)p*DD + d)     = make_float2(c[mt][n2][0], c[mt][n2][1]);
            *(float2*)(out_x + (size_t)(p+8)*DD + d) = make_float2(c[mt][n2][2], c[mt][n2][3]);
        }
    }
}

// ---------------------------------------------------------------------------
extern "C" void kernel_launch(void* const* d_in, const int* in_sizes, int n_in,
                              void* d_out, int out_size) {
    const float* z       = (const float*)d_in[0];
    const float* mask    = (const float*)d_in[1];
    const float* ln_in_w = (const float*)d_in[2];
    const float* ln_in_b = (const float*)d_in[3];
    const float* w_ab_p  = (const float*)d_in[4];
    const float* b_ab_p  = (const float*)d_in[5];
    const float* w_ab_g  = (const float*)d_in[6];
    const float* b_ab_g  = (const float*)d_in[7];
    const float* w_g     = (const float*)d_in[8];
    const float* ln_out_w= (const float*)d_in[9];
    const float* ln_out_b= (const float*)d_in[10];
    const float* w_z     = (const float*)d_in[11];

    float* out_x = (float*)d_out;
    float* out_g = (out_size >= 2*NP*DD) ? (out_x + (size_t)NP*DD) : nullptr;

    const int projSmem = (128*132 + 2*128*36 + 64*132) * 4;  // 138240
    const int triSmem  = 2 * 2 * 128*36 * 4;                 // 73728
    const int outSmem  = (128*132 + 128*36) * 4;             // 86016
    cudaFuncSetAttribute(proj_kernel, cudaFuncAttributeMaxDynamicSharedMemorySize, projSmem);
    cudaFuncSetAttribute(tri_kernel,  cudaFuncAttributeMaxDynamicSharedMemorySize, triSmem);
    cudaFuncSetAttribute(out_kernel,  cudaFuncAttributeMaxDynamicSharedMemorySize, outSmem);

    prep_w<<<320, 256>>>(w_g, w_ab_p, w_ab_g);
    ln_in_kernel<<<NP/8, 256>>>(z, ln_in_w, ln_in_b);
    proj_kernel<<<NP/128, 256, projSmem>>>(mask, b_ab_p, b_ab_g, out_g);
    tri_kernel<<<dim3(16, 128), 256, triSmem>>>();
    out_kernel<<<NP/128, 256, outSmem>>>(ln_out_w, ln_out_b, w_z, out_x);
}

// round 9
// speedup vs baseline: 2.9670x; 1.0746x over previous
#include <cuda_runtime.h>
#include <cstdint>
#include <math.h>

#define NN 512
#define DD 128
#define NP (NN*NN)

__device__ float g_a [(size_t)DD*NP];   // a, tf32-rounded, head-major [h][i*N+k]
__device__ float g_b [(size_t)DD*NP];   // b, tf32-rounded, head-major [h][j*N+k]
__device__ float g_x [(size_t)DD*NP];   // triangle result f32, head-major
__device__ float g_w [640*DD];          // virtual weight matrix, tf32-rounded

// ---------------------------------------------------------------------------
__device__ __forceinline__ float tf32f(float f){
    uint32_t u; asm("cvt.rna.tf32.f32 %0, %1;" : "=r"(u) : "f"(f));
    return __uint_as_float(u);
}
__device__ __forceinline__ void mma8(float c[4], uint32_t a0, uint32_t a1,
                                     uint32_t a2, uint32_t a3,
                                     uint32_t b0, uint32_t b1){
    asm volatile(
        "mma.sync.aligned.m16n8k8.row.col.f32.tf32.tf32.f32 "
        "{%0,%1,%2,%3}, {%4,%5,%6,%7}, {%8,%9}, {%0,%1,%2,%3};"
        : "+f"(c[0]), "+f"(c[1]), "+f"(c[2]), "+f"(c[3])
        : "r"(a0), "r"(a1), "r"(a2), "r"(a3), "r"(b0), "r"(b1));
}
__device__ __forceinline__ uint32_t smem_u32(const void* p){
    uint32_t a;
    asm("{ .reg .u64 t; cvta.to.shared.u64 t, %1; cvt.u32.u64 %0, t; }" : "=r"(a) : "l"(p));
    return a;
}
__device__ __forceinline__ void cp16(uint32_t dst, const float* src){
    asm volatile("cp.async.cg.shared.global [%0], [%1], 16;" :: "r"(dst), "l"(src) : "memory");
}
#define CP_COMMIT() asm volatile("cp.async.commit_group;" ::: "memory")
#define CP_WAIT0()  asm volatile("cp.async.wait_group 0;" ::: "memory")
#define CP_WAIT1()  asm volatile("cp.async.wait_group 1;" ::: "memory")

// ---------------------------------------------------------------------------
// prep_w: tf32-rounded virtual weight matrix.
// rows 0..127 = w_g ; 128+2t = w_ab_p[t] ; 129+2t = w_ab_g[t].
// ---------------------------------------------------------------------------
__global__ void prep_w(const float* __restrict__ wg,
                       const float* __restrict__ wap,
                       const float* __restrict__ wag){
    int idx = blockIdx.x*256 + threadIdx.x;      // 81920 total
    int row = idx >> 7, col = idx & 127;
    const float* src;
    if (row < 128) src = wg + row*DD;
    else { int t = (row-128)>>1; src = (row & 1) ? (wag + t*DD) : (wap + t*DD); }
    g_w[idx] = tf32f(src[col]);
}

// ---------------------------------------------------------------------------
// proj: 64 pixels per CTA. Fused input-LN (reads z directly). A tile resident
// in smem; 20 K-chunks of the 640-row W matrix streamed through a 3-stage
// cp.async ring with ONE barrier per chunk.
// smem: A[64][132] | W 3x[128][36] | stage[64][68]  = 106496 B  (2 CTA/SM)
// ---------------------------------------------------------------------------
__global__ __launch_bounds__(256)
void proj_kernel(const float* __restrict__ z,
                 const float* __restrict__ lnw, const float* __restrict__ lnb,
                 const float* __restrict__ mask,
                 const float* __restrict__ b_ab_p, const float* __restrict__ b_ab_g,
                 float* __restrict__ out_g) {
    extern __shared__ float sh[];
    float* As    = sh;                    // [64][132]
    float* Wb    = sh + 64*132;           // 3 x [128][36]
    float* stage = Wb + 3*128*36;         // [64][68]
    const int tid = threadIdx.x, warp = tid>>5, lane = tid&31;
    const int grp = lane>>2, qid = lane&3;
    const int wm = warp>>2, wn = warp&3;  // 2 x 4 warps
    const int mB = wm*32, nB = wn*32;
    const int pBase = blockIdx.x*64;
    uint32_t sW = smem_u32(Wb);

    // prefetch W chunks 0 and 1 (one group each)
    #pragma unroll
    for (int t = 0; t < 4; t++){
        int idx = tid + t*256, r = idx >> 3, seg = idx & 7;
        cp16(sW + (uint32_t)(r*144 + seg*16), g_w + (size_t)r*DD + seg*4);
    }
    CP_COMMIT();
    #pragma unroll
    for (int t = 0; t < 4; t++){
        int idx = tid + t*256, r = idx >> 3, seg = idx & 7;
        cp16(sW + (uint32_t)(18432 + r*144 + seg*16), g_w + (size_t)r*DD + 32 + seg*4);
    }
    CP_COMMIT();

    // fused input LayerNorm: one warp per pixel row, 8 rows per pass
    {
        float4 wv = ((const float4*)lnw)[lane];
        float4 bv = ((const float4*)lnb)[lane];
        #pragma unroll
        for (int it = 0; it < 8; it++) {
            int pr = it*8 + warp;
            float4 v = ((const float4*)(z + (size_t)(pBase+pr)*DD))[lane];
            float s  = v.x + v.y + v.z + v.w;
            float sq = v.x*v.x + v.y*v.y + v.z*v.z + v.w*v.w;
            #pragma unroll
            for (int o = 16; o > 0; o >>= 1) {
                s  += __shfl_xor_sync(0xffffffffu, s,  o);
                sq += __shfl_xor_sync(0xffffffffu, sq, o);
            }
            float mean = s * (1.0f/128.0f);
            float var  = sq * (1.0f/128.0f) - mean*mean;
            float rs   = rsqrtf(var + 1e-5f);
            float* d = As + pr*132 + lane*4;
            d[0] = tf32f((v.x-mean)*rs*wv.x + bv.x);
            d[1] = tf32f((v.y-mean)*rs*wv.y + bv.y);
            d[2] = tf32f((v.z-mean)*rs*wv.z + bv.z);
            d[3] = tf32f((v.w-mean)*rs*wv.w + bv.w);
        }
    }

    float c[2][4][4];
    for (int ci = 0; ci < 20; ci++) {
        if ((ci & 3) == 0) {
            #pragma unroll
            for (int a = 0; a < 2; a++)
                #pragma unroll
                for (int b = 0; b < 4; b++)
                    #pragma unroll
                    for (int d = 0; d < 4; d++) c[a][b][d] = 0.f;
        }
        if (ci == 19) CP_WAIT0(); else CP_WAIT1();
        __syncthreads();                      // chunk ci visible; ci-1 fully consumed
        if (ci + 2 < 20) {
            int cj = ci + 2;
            uint32_t dst = sW + (uint32_t)((cj % 3) * 18432);
            const float* src = g_w + (size_t)(cj>>2)*128*DD + (cj&3)*32;
            #pragma unroll
            for (int t = 0; t < 4; t++){
                int idx = tid + t*256, r = idx >> 3, seg = idx & 7;
                cp16(dst + (uint32_t)(r*144 + seg*16), src + (size_t)r*DD + seg*4);
            }
            CP_COMMIT();
        }
        const float* Ws = Wb + (ci % 3) * 4608;
        #pragma unroll
        for (int ks = 0; ks < 4; ks++) {
            int k0w = ks*8, k0a = (ci&3)*32 + ks*8;
            uint32_t bf[4][2];
            #pragma unroll
            for (int n2 = 0; n2 < 4; n2++) {
                int rowb = (nB + n2*8 + grp)*36 + k0w + qid;
                bf[n2][0] = __float_as_uint(Ws[rowb]);
                bf[n2][1] = __float_as_uint(Ws[rowb + 4]);
            }
            #pragma unroll
            for (int mt = 0; mt < 2; mt++) {
                int rowa = (mB + mt*16 + grp)*132 + k0a + qid;
                uint32_t a0 = __float_as_uint(As[rowa]);
                uint32_t a1 = __float_as_uint(As[rowa + 8*132]);
                uint32_t a2 = __float_as_uint(As[rowa + 4]);
                uint32_t a3 = __float_as_uint(As[rowa + 8*132 + 4]);
                #pragma unroll
                for (int n2 = 0; n2 < 4; n2++)
                    mma8(c[mt][n2], a0, a1, a2, a3, bf[n2][0], bf[n2][1]);
            }
        }
        if ((ci & 3) == 3) {
            int nt = ci >> 2;
            if (nt == 0) {
                if (out_g != nullptr) {
                    #pragma unroll
                    for (int mt = 0; mt < 2; mt++) {
                        int p = pBase + mB + mt*16 + grp;
                        #pragma unroll
                        for (int n2 = 0; n2 < 4; n2++) {
                            int O = nB + n2*8 + 2*qid;
                            *(float2*)(out_g + (size_t)p*DD + O)     = make_float2(c[mt][n2][0], c[mt][n2][1]);
                            *(float2*)(out_g + (size_t)(p+8)*DD + O) = make_float2(c[mt][n2][2], c[mt][n2][3]);
                        }
                    }
                }
            } else {
                int tB = (nt-1)*64;
                const float msc = 0.044194173824159216f;
                #pragma unroll
                for (int mt = 0; mt < 2; mt++) {
                    int px = mB + mt*16 + grp;
                    float mv0 = mask[pBase + px] * msc;
                    float mv1 = mask[pBase + px + 8] * msc;
                    #pragma unroll
                    for (int n2 = 0; n2 < 4; n2++) {
                        int tl = wn*16 + n2*4 + qid;
                        float bp = b_ab_p[tB + tl];
                        float bg = b_ab_g[tB + tl];
                        float v0 = tf32f((c[mt][n2][0] + bp) * mv0 *
                                         (1.0f/(1.0f + __expf(-(c[mt][n2][1] + bg)))));
                        float v1 = tf32f((c[mt][n2][2] + bp) * mv1 *
                                         (1.0f/(1.0f + __expf(-(c[mt][n2][3] + bg)))));
                        stage[tl*68 + px]     = v0;
                        stage[tl*68 + px + 8] = v1;
                    }
                }
                __syncthreads();
                float* dstM = (tB < 128) ? g_a : g_b;
                int rowB = tB & 127;
                #pragma unroll
                for (int k = 0; k < 4; k++) {
                    int idx = tid + k*256, rr = idx >> 4, c4 = (idx & 15)*4;
                    *(float4*)(dstM + (size_t)(rowB + rr)*NP + pBase + c4) =
                        *(const float4*)(stage + rr*68 + c4);
                }
            }
        }
    }
}

// ---------------------------------------------------------------------------
// tri: head h: X_h = A_h · B_h^T, 128x128 C tile, K=512 in 16 chunks of 32
// through a 3-stage cp.async ring, ONE barrier per chunk.
// smem: 3 x (A[128][36] + B[128][36]) = 110592 B
// ---------------------------------------------------------------------------
__global__ __launch_bounds__(256)
void tri_kernel() {
    extern __shared__ float sh[];
    const int tid = threadIdx.x, warp = tid>>5, lane = tid&31;
    const int grp = lane>>2, qid = lane&3;
    const int wm = warp>>2, wn = warp&3;
    const int mB = wm*64, nB = wn*32;
    int h  = blockIdx.y;
    int i0 = (blockIdx.x >> 2) * 128;
    int j0 = (blockIdx.x & 3) * 128;
    const float* A = g_a + (size_t)h*NP + (size_t)i0*NN;
    const float* B = g_b + (size_t)h*NP + (size_t)j0*NN;
    uint32_t s0 = smem_u32(sh);

    // prefetch chunks 0 and 1
    #pragma unroll
    for (int t = 0; t < 4; t++){
        int idx = tid + t*256, r = idx >> 3, seg = idx & 7;
        cp16(s0 + (uint32_t)(r*144 + seg*16),         A + (size_t)r*NN + seg*4);
        cp16(s0 + (uint32_t)(18432 + r*144 + seg*16), B + (size_t)r*NN + seg*4);
    }
    CP_COMMIT();
    #pragma unroll
    for (int t = 0; t < 4; t++){
        int idx = tid + t*256, r = idx >> 3, seg = idx & 7;
        cp16(s0 + (uint32_t)(36864 + r*144 + seg*16),         A + (size_t)r*NN + 32 + seg*4);
        cp16(s0 + (uint32_t)(36864 + 18432 + r*144 + seg*16), B + (size_t)r*NN + 32 + seg*4);
    }
    CP_COMMIT();

    float c[4][4][4];
    #pragma unroll
    for (int a = 0; a < 4; a++)
        #pragma unroll
        for (int b = 0; b < 4; b++)
            #pragma unroll
            for (int d = 0; d < 4; d++) c[a][b][d] = 0.f;

    for (int kc = 0; kc < 16; kc++) {
        if (kc == 15) CP_WAIT0(); else CP_WAIT1();
        __syncthreads();
        if (kc + 2 < 16) {
            int cj = kc + 2;
            uint32_t dst = s0 + (uint32_t)((cj % 3) * 36864);
            const float* As_ = A + cj*32;
            const float* Bs_ = B + cj*32;
            #pragma unroll
            for (int t = 0; t < 4; t++){
                int idx = tid + t*256, r = idx >> 3, seg = idx & 7;
                cp16(dst + (uint32_t)(r*144 + seg*16),         As_ + (size_t)r*NN + seg*4);
                cp16(dst + (uint32_t)(18432 + r*144 + seg*16), Bs_ + (size_t)r*NN + seg*4);
            }
            CP_COMMIT();
        }
        const float* Asm = sh + (kc % 3) * 9216;
        const float* Bsm = Asm + 4608;
        #pragma unroll
        for (int ks = 0; ks < 4; ks++) {
            int k0 = ks*8;
            uint32_t bf[4][2];
            #pragma unroll
            for (int n2 = 0; n2 < 4; n2++) {
                int rowb = (nB + n2*8 + grp)*36 + k0 + qid;
                bf[n2][0] = __float_as_uint(Bsm[rowb]);
                bf[n2][1] = __float_as_uint(Bsm[rowb + 4]);
            }
            #pragma unroll
            for (int mt = 0; mt < 4; mt++) {
                int rowa = (mB + mt*16 + grp)*36 + k0 + qid;
                uint32_t a0 = __float_as_uint(Asm[rowa]);
                uint32_t a1 = __float_as_uint(Asm[rowa + 8*36]);
                uint32_t a2 = __float_as_uint(Asm[rowa + 4]);
                uint32_t a3 = __float_as_uint(Asm[rowa + 8*36 + 4]);
                #pragma unroll
                for (int n2 = 0; n2 < 4; n2++)
                    mma8(c[mt][n2], a0, a1, a2, a3, bf[n2][0], bf[n2][1]);
            }
        }
    }
    float* X = g_x + (size_t)h*NP;
    #pragma unroll
    for (int mt = 0; mt < 4; mt++) {
        int row = i0 + mB + mt*16 + grp;
        #pragma unroll
        for (int n2 = 0; n2 < 4; n2++) {
            int col = j0 + nB + n2*8 + 2*qid;
            *(float2*)(X + (size_t)row*NN + col)     = make_float2(c[mt][n2][0], c[mt][n2][1]);
            *(float2*)(X + (size_t)(row+8)*NN + col) = make_float2(c[mt][n2][2], c[mt][n2][3]);
        }
    }
}

// ---------------------------------------------------------------------------
// out: gather-transpose + LN over H + GEMM vs w_z (tf32 mma).
// smem: xt[128][132] + ws[128][36]  = 86016 B
// ---------------------------------------------------------------------------
__global__ __launch_bounds__(256)
void out_kernel(const float* __restrict__ lnw,
                const float* __restrict__ lnb,
                const float* __restrict__ w_z,
                float* __restrict__ out_x) {
    extern __shared__ float xs[];
    float* xt = xs;                // [128 px][132]
    float* ws = xs + 128*132;      // [128 d][36] per chunk
    int tid = threadIdx.x, warp = tid >> 5, lane = tid & 31;
    int grp = lane >> 2, qid = lane & 3;
    int p0 = blockIdx.x * 128;

    int cpx = tid & 127, hh0 = tid >> 7;
    for (int hb = 0; hb < 128; hb += 2) {
        int h_ = hb + hh0;
        xt[cpx*132 + h_] = g_x[(size_t)h_*NP + p0 + cpx];
    }
    __syncthreads();

    float4 wv  = ((const float4*)lnw)[lane];
    float4 bvv = ((const float4*)lnb)[lane];
    for (int pp = 0; pp < 16; pp++) {
        int p = warp*16 + pp;
        float4 v = *(float4*)(xt + p*132 + lane*4);
        float s  = v.x + v.y + v.z + v.w;
        float sq = v.x*v.x + v.y*v.y + v.z*v.z + v.w*v.w;
        #pragma unroll
        for (int o = 16; o > 0; o >>= 1) {
            s  += __shfl_xor_sync(0xffffffffu, s,  o);
            sq += __shfl_xor_sync(0xffffffffu, sq, o);
        }
        float mean = s * (1.0f/128.0f);
        float var  = sq * (1.0f/128.0f) - mean*mean;
        float rs   = rsqrtf(var + 1e-5f);
        float* d = xt + p*132 + lane*4;
        d[0] = tf32f((v.x-mean)*rs*wv.x + bvv.x);
        d[1] = tf32f((v.y-mean)*rs*wv.y + bvv.y);
        d[2] = tf32f((v.z-mean)*rs*wv.z + bvv.z);
        d[3] = tf32f((v.w-mean)*rs*wv.w + bvv.w);
    }
    __syncthreads();

    int wm = warp >> 2, wn = warp & 3;
    int mB = wm*64, nB = wn*32;
    float c[4][4][4];
    #pragma unroll
    for (int a = 0; a < 4; a++)
        #pragma unroll
        for (int b = 0; b < 4; b++)
            #pragma unroll
            for (int d = 0; d < 4; d++) c[a][b][d] = 0.f;

    int r = tid >> 3, cc = (tid & 7) << 2;
    for (int kc = 0; kc < 4; kc++) {
        #pragma unroll
        for (int k = 0; k < 4; k++) {
            int rr = r + k*32;
            float4 v = *(const float4*)(w_z + rr*DD + kc*32 + cc);
            float* pw = ws + rr*36 + cc;
            pw[0]=tf32f(v.x); pw[1]=tf32f(v.y); pw[2]=tf32f(v.z); pw[3]=tf32f(v.w);
        }
        __syncthreads();
        #pragma unroll
        for (int ks = 0; ks < 4; ks++) {
            int k0w = ks*8;
            int k0a = kc*32 + ks*8;
            uint32_t bf[4][2];
            #pragma unroll
            for (int n2 = 0; n2 < 4; n2++) {
                int rowb = (nB + n2*8 + grp)*36 + k0w + qid;
                bf[n2][0] = __float_as_uint(ws[rowb]);
                bf[n2][1] = __float_as_uint(ws[rowb + 4]);
            }
            #pragma unroll
            for (int mt = 0; mt < 4; mt++) {
                int rowa = (mB + mt*16 + grp)*132 + k0a + qid;
                uint32_t a0 = __float_as_uint(xt[rowa]);
                uint32_t a1 = __float_as_uint(xt[rowa + 8*132]);
                uint32_t a2 = __float_as_uint(xt[rowa + 4]);
                uint32_t a3 = __float_as_uint(xt[rowa + 8*132 + 4]);
                #pragma unroll
                for (int n2 = 0; n2 < 4; n2++)
                    mma8(c[mt][n2], a0, a1, a2, a3, bf[n2][0], bf[n2][1]);
            }
        }
        __syncthreads();
    }
    #pragma unroll
    for (int mt = 0; mt < 4; mt++) {
        int p = p0 + mB + mt*16 + grp;
        #pragma unroll
        for (int n2 = 0; n2 < 4; n2++) {
            int d = nB + n2*8 + 2*qid;
            *(float2*)(out_x + (size_t)p*DD + d)     = make_float2(c[mt][n2][0], c[mt][n2][1]);
            *(float2*)(out_x + (size_t)(p+8)*DD + d) = make_float2(c[mt][n2][2], c[mt][n2][3]);
        }
    }
}

// ---------------------------------------------------------------------------
extern "C" void kernel_launch(void* const* d_in, const int* in_sizes, int n_in,
                              void* d_out, int out_size) {
    const float* z       = (const float*)d_in[0];
    const float* mask    = (const float*)d_in[1];
    const float* ln_in_w = (const float*)d_in[2];
    const float* ln_in_b = (const float*)d_in[3];
    const float* w_ab_p  = (const float*)d_in[4];
    const float* b_ab_p  = (const float*)d_in[5];
    const float* w_ab_g  = (const float*)d_in[6];
    const float* b_ab_g  = (const float*)d_in[7];
    const float* w_g     = (const float*)d_in[8];
    const float* ln_out_w= (const float*)d_in[9];
    const float* ln_out_b= (const float*)d_in[10];
    const float* w_z     = (const float*)d_in[11];

    float* out_x = (float*)d_out;
    float* out_g = (out_size >= 2*NP*DD) ? (out_x + (size_t)NP*DD) : nullptr;

    const int projSmem = (64*132 + 3*128*36 + 64*68) * 4;   // 106496
    const int triSmem  = 3 * 2 * 128*36 * 4;                // 110592
    const int outSmem  = (128*132 + 128*36) * 4;            // 86016
    cudaFuncSetAttribute(proj_kernel, cudaFuncAttributeMaxDynamicSharedMemorySize, projSmem);
    cudaFuncSetAttribute(tri_kernel,  cudaFuncAttributeMaxDynamicSharedMemorySize, triSmem);
    cudaFuncSetAttribute(out_kernel,  cudaFuncAttributeMaxDynamicSharedMemorySize, outSmem);

    prep_w<<<320, 256>>>(w_g, w_ab_p, w_ab_g);
    proj_kernel<<<NP/64, 256, projSmem>>>(z, ln_in_w, ln_in_b, mask, b_ab_p, b_ab_g, out_g);
    tri_kernel<<<dim3(16, 128), 256, triSmem>>>();
    out_kernel<<<NP/128, 256, outSmem>>>(ln_out_w, ln_out_b, w_z, out_x);
}

// round 10
// speedup vs baseline: 3.0747x; 1.0363x over previous
#include <cuda_runtime.h>
#include <cstdint>
#include <math.h>

#define NN 512
#define DD 128
#define NP (NN*NN)

__device__ float g_a [(size_t)DD*NP];   // a, tf32-rounded, head-major [h][i*N+k]
__device__ float g_b [(size_t)DD*NP];   // b, tf32-rounded, head-major [h][j*N+k]
__device__ float g_x [(size_t)DD*NP];   // triangle result f32, head-major
__device__ float g_w [640*DD];          // virtual weight matrix, tf32-rounded

// ---------------------------------------------------------------------------
__device__ __forceinline__ float tf32f(float f){
    uint32_t u; asm("cvt.rna.tf32.f32 %0, %1;" : "=r"(u) : "f"(f));
    return __uint_as_float(u);
}
__device__ __forceinline__ void mma8(float c[4], uint32_t a0, uint32_t a1,
                                     uint32_t a2, uint32_t a3,
                                     uint32_t b0, uint32_t b1){
    asm volatile(
        "mma.sync.aligned.m16n8k8.row.col.f32.tf32.tf32.f32 "
        "{%0,%1,%2,%3}, {%4,%5,%6,%7}, {%8,%9}, {%0,%1,%2,%3};"
        : "+f"(c[0]), "+f"(c[1]), "+f"(c[2]), "+f"(c[3])
        : "r"(a0), "r"(a1), "r"(a2), "r"(a3), "r"(b0), "r"(b1));
}
__device__ __forceinline__ uint32_t smem_u32(const void* p){
    uint32_t a;
    asm("{ .reg .u64 t; cvta.to.shared.u64 t, %1; cvt.u32.u64 %0, t; }" : "=r"(a) : "l"(p));
    return a;
}
__device__ __forceinline__ void cp16(uint32_t dst, const float* src){
    asm volatile("cp.async.cg.shared.global [%0], [%1], 16;" :: "r"(dst), "l"(src) : "memory");
}
#define CP_COMMIT() asm volatile("cp.async.commit_group;" ::: "memory")
#define CP_WAIT0()  asm volatile("cp.async.wait_group 0;" ::: "memory")
#define CP_WAIT1()  asm volatile("cp.async.wait_group 1;" ::: "memory")

// ---------------------------------------------------------------------------
// prep_w: tf32-rounded virtual weight matrix.
// rows 0..127 = w_g ; 128+2t = w_ab_p[t] ; 129+2t = w_ab_g[t].
// ---------------------------------------------------------------------------
__global__ void prep_w(const float* __restrict__ wg,
                       const float* __restrict__ wap,
                       const float* __restrict__ wag){
    int idx = blockIdx.x*256 + threadIdx.x;      // 81920 total
    int row = idx >> 7, col = idx & 127;
    const float* src;
    if (row < 128) src = wg + row*DD;
    else { int t = (row-128)>>1; src = (row & 1) ? (wag + t*DD) : (wap + t*DD); }
    g_w[idx] = tf32f(src[col]);
}

// ---------------------------------------------------------------------------
// proj: 64 pixels per CTA. Fused input-LN (batched MLP=8). A tile resident;
// 20 W K-chunks through 3-stage cp.async ring, one barrier per chunk.
// smem: A[64][132] | W 3x[128][36] | stage[64][68]  = 106496 B  (2 CTA/SM)
// ---------------------------------------------------------------------------
__global__ __launch_bounds__(256)
void proj_kernel(const float* __restrict__ z,
                 const float* __restrict__ lnw, const float* __restrict__ lnb,
                 const float* __restrict__ mask,
                 const float* __restrict__ b_ab_p, const float* __restrict__ b_ab_g,
                 float* __restrict__ out_g) {
    extern __shared__ float sh[];
    float* As    = sh;                    // [64][132]
    float* Wb    = sh + 64*132;           // 3 x [128][36]
    float* stage = Wb + 3*128*36;         // [64][68]
    const int tid = threadIdx.x, warp = tid>>5, lane = tid&31;
    const int grp = lane>>2, qid = lane&3;
    const int wm = warp>>2, wn = warp&3;  // 2 x 4 warps
    const int mB = wm*32, nB = wn*32;
    const int pBase = blockIdx.x*64;
    uint32_t sW = smem_u32(Wb);

    // prefetch W chunks 0 and 1 (one group each)
    #pragma unroll
    for (int t = 0; t < 4; t++){
        int idx = tid + t*256, r = idx >> 3, seg = idx & 7;
        cp16(sW + (uint32_t)(r*144 + seg*16), g_w + (size_t)r*DD + seg*4);
    }
    CP_COMMIT();
    #pragma unroll
    for (int t = 0; t < 4; t++){
        int idx = tid + t*256, r = idx >> 3, seg = idx & 7;
        cp16(sW + (uint32_t)(18432 + r*144 + seg*16), g_w + (size_t)r*DD + 32 + seg*4);
    }
    CP_COMMIT();

    // fused input LayerNorm — batched: 8 LDGs in flight, 8 interleaved chains
    {
        float4 wv = ((const float4*)lnw)[lane];
        float4 bv = ((const float4*)lnb)[lane];
        float4 vv[8];
        #pragma unroll
        for (int it = 0; it < 8; it++)
            vv[it] = ((const float4*)(z + (size_t)(pBase + it*8 + warp)*DD))[lane];
        float s[8], sq[8];
        #pragma unroll
        for (int it = 0; it < 8; it++) {
            float4 v = vv[it];
            s[it]  = v.x + v.y + v.z + v.w;
            sq[it] = v.x*v.x + v.y*v.y + v.z*v.z + v.w*v.w;
        }
        #pragma unroll
        for (int o = 16; o > 0; o >>= 1) {
            #pragma unroll
            for (int it = 0; it < 8; it++) {
                s[it]  += __shfl_xor_sync(0xffffffffu, s[it],  o);
                sq[it] += __shfl_xor_sync(0xffffffffu, sq[it], o);
            }
        }
        #pragma unroll
        for (int it = 0; it < 8; it++) {
            float mean = s[it] * (1.0f/128.0f);
            float var  = sq[it] * (1.0f/128.0f) - mean*mean;
            float rs   = rsqrtf(var + 1e-5f);
            float4 v = vv[it];
            float* d = As + (it*8 + warp)*132 + lane*4;
            d[0] = tf32f((v.x-mean)*rs*wv.x + bv.x);
            d[1] = tf32f((v.y-mean)*rs*wv.y + bv.y);
            d[2] = tf32f((v.z-mean)*rs*wv.z + bv.z);
            d[3] = tf32f((v.w-mean)*rs*wv.w + bv.w);
        }
    }

    float c[2][4][4];
    for (int ci = 0; ci < 20; ci++) {
        if ((ci & 3) == 0) {
            #pragma unroll
            for (int a = 0; a < 2; a++)
                #pragma unroll
                for (int b = 0; b < 4; b++)
                    #pragma unroll
                    for (int d = 0; d < 4; d++) c[a][b][d] = 0.f;
        }
        if (ci == 19) CP_WAIT0(); else CP_WAIT1();
        __syncthreads();                      // chunk ci visible; ci-1 fully consumed
        if (ci + 2 < 20) {
            int cj = ci + 2;
            uint32_t dst = sW + (uint32_t)((cj % 3) * 18432);
            const float* src = g_w + (size_t)(cj>>2)*128*DD + (cj&3)*32;
            #pragma unroll
            for (int t = 0; t < 4; t++){
                int idx = tid + t*256, r = idx >> 3, seg = idx & 7;
                cp16(dst + (uint32_t)(r*144 + seg*16), src + (size_t)r*DD + seg*4);
            }
            CP_COMMIT();
        }
        const float* Ws = Wb + (ci % 3) * 4608;
        #pragma unroll
        for (int ks = 0; ks < 4; ks++) {
            int k0w = ks*8, k0a = (ci&3)*32 + ks*8;
            uint32_t bf[4][2];
            #pragma unroll
            for (int n2 = 0; n2 < 4; n2++) {
                int rowb = (nB + n2*8 + grp)*36 + k0w + qid;
                bf[n2][0] = __float_as_uint(Ws[rowb]);
                bf[n2][1] = __float_as_uint(Ws[rowb + 4]);
            }
            #pragma unroll
            for (int mt = 0; mt < 2; mt++) {
                int rowa = (mB + mt*16 + grp)*132 + k0a + qid;
                uint32_t a0 = __float_as_uint(As[rowa]);
                uint32_t a1 = __float_as_uint(As[rowa + 8*132]);
                uint32_t a2 = __float_as_uint(As[rowa + 4]);
                uint32_t a3 = __float_as_uint(As[rowa + 8*132 + 4]);
                #pragma unroll
                for (int n2 = 0; n2 < 4; n2++)
                    mma8(c[mt][n2], a0, a1, a2, a3, bf[n2][0], bf[n2][1]);
            }
        }
        if ((ci & 3) == 3) {
            int nt = ci >> 2;
            if (nt == 0) {
                if (out_g != nullptr) {
                    #pragma unroll
                    for (int mt = 0; mt < 2; mt++) {
                        int p = pBase + mB + mt*16 + grp;
                        #pragma unroll
                        for (int n2 = 0; n2 < 4; n2++) {
                            int O = nB + n2*8 + 2*qid;
                            *(float2*)(out_g + (size_t)p*DD + O)     = make_float2(c[mt][n2][0], c[mt][n2][1]);
                            *(float2*)(out_g + (size_t)(p+8)*DD + O) = make_float2(c[mt][n2][2], c[mt][n2][3]);
                        }
                    }
                }
            } else {
                int tB = (nt-1)*64;
                const float msc = 0.044194173824159216f;
                #pragma unroll
                for (int mt = 0; mt < 2; mt++) {
                    int px = mB + mt*16 + grp;
                    float mv0 = mask[pBase + px] * msc;
                    float mv1 = mask[pBase + px + 8] * msc;
                    #pragma unroll
                    for (int n2 = 0; n2 < 4; n2++) {
                        int tl = wn*16 + n2*4 + qid;
                        float bp = b_ab_p[tB + tl];
                        float bg = b_ab_g[tB + tl];
                        float v0 = tf32f((c[mt][n2][0] + bp) * mv0 *
                                         (1.0f/(1.0f + __expf(-(c[mt][n2][1] + bg)))));
                        float v1 = tf32f((c[mt][n2][2] + bp) * mv1 *
                                         (1.0f/(1.0f + __expf(-(c[mt][n2][3] + bg)))));
                        stage[tl*68 + px]     = v0;
                        stage[tl*68 + px + 8] = v1;
                    }
                }
                __syncthreads();
                float* dstM = (tB < 128) ? g_a : g_b;
                int rowB = tB & 127;
                #pragma unroll
                for (int k = 0; k < 4; k++) {
                    int idx = tid + k*256, rr = idx >> 4, c4 = (idx & 15)*4;
                    *(float4*)(dstM + (size_t)(rowB + rr)*NP + pBase + c4) =
                        *(const float4*)(stage + rr*68 + c4);
                }
            }
        }
    }
}

// ---------------------------------------------------------------------------
// tri: head h: X_h = A_h · B_h^T, 128x128 C tile, K=512 in 16 chunks of 32
// through a 3-stage cp.async ring, ONE barrier per chunk. (unchanged)
// smem: 3 x (A[128][36] + B[128][36]) = 110592 B
// ---------------------------------------------------------------------------
__global__ __launch_bounds__(256)
void tri_kernel() {
    extern __shared__ float sh[];
    const int tid = threadIdx.x, warp = tid>>5, lane = tid&31;
    const int grp = lane>>2, qid = lane&3;
    const int wm = warp>>2, wn = warp&3;
    const int mB = wm*64, nB = wn*32;
    int h  = blockIdx.y;
    int i0 = (blockIdx.x >> 2) * 128;
    int j0 = (blockIdx.x & 3) * 128;
    const float* A = g_a + (size_t)h*NP + (size_t)i0*NN;
    const float* B = g_b + (size_t)h*NP + (size_t)j0*NN;
    uint32_t s0 = smem_u32(sh);

    #pragma unroll
    for (int t = 0; t < 4; t++){
        int idx = tid + t*256, r = idx >> 3, seg = idx & 7;
        cp16(s0 + (uint32_t)(r*144 + seg*16),         A + (size_t)r*NN + seg*4);
        cp16(s0 + (uint32_t)(18432 + r*144 + seg*16), B + (size_t)r*NN + seg*4);
    }
    CP_COMMIT();
    #pragma unroll
    for (int t = 0; t < 4; t++){
        int idx = tid + t*256, r = idx >> 3, seg = idx & 7;
        cp16(s0 + (uint32_t)(36864 + r*144 + seg*16),         A + (size_t)r*NN + 32 + seg*4);
        cp16(s0 + (uint32_t)(36864 + 18432 + r*144 + seg*16), B + (size_t)r*NN + 32 + seg*4);
    }
    CP_COMMIT();

    float c[4][4][4];
    #pragma unroll
    for (int a = 0; a < 4; a++)
        #pragma unroll
        for (int b = 0; b < 4; b++)
            #pragma unroll
            for (int d = 0; d < 4; d++) c[a][b][d] = 0.f;

    for (int kc = 0; kc < 16; kc++) {
        if (kc == 15) CP_WAIT0(); else CP_WAIT1();
        __syncthreads();
        if (kc + 2 < 16) {
            int cj = kc + 2;
            uint32_t dst = s0 + (uint32_t)((cj % 3) * 36864);
            const float* As_ = A + cj*32;
            const float* Bs_ = B + cj*32;
            #pragma unroll
            for (int t = 0; t < 4; t++){
                int idx = tid + t*256, r = idx >> 3, seg = idx & 7;
                cp16(dst + (uint32_t)(r*144 + seg*16),         As_ + (size_t)r*NN + seg*4);
                cp16(dst + (uint32_t)(18432 + r*144 + seg*16), Bs_ + (size_t)r*NN + seg*4);
            }
            CP_COMMIT();
        }
        const float* Asm = sh + (kc % 3) * 9216;
        const float* Bsm = Asm + 4608;
        #pragma unroll
        for (int ks = 0; ks < 4; ks++) {
            int k0 = ks*8;
            uint32_t bf[4][2];
            #pragma unroll
            for (int n2 = 0; n2 < 4; n2++) {
                int rowb = (nB + n2*8 + grp)*36 + k0 + qid;
                bf[n2][0] = __float_as_uint(Bsm[rowb]);
                bf[n2][1] = __float_as_uint(Bsm[rowb + 4]);
            }
            #pragma unroll
            for (int mt = 0; mt < 4; mt++) {
                int rowa = (mB + mt*16 + grp)*36 + k0 + qid;
                uint32_t a0 = __float_as_uint(Asm[rowa]);
                uint32_t a1 = __float_as_uint(Asm[rowa + 8*36]);
                uint32_t a2 = __float_as_uint(Asm[rowa + 4]);
                uint32_t a3 = __float_as_uint(Asm[rowa + 8*36 + 4]);
                #pragma unroll
                for (int n2 = 0; n2 < 4; n2++)
                    mma8(c[mt][n2], a0, a1, a2, a3, bf[n2][0], bf[n2][1]);
            }
        }
    }
    float* X = g_x + (size_t)h*NP;
    #pragma unroll
    for (int mt = 0; mt < 4; mt++) {
        int row = i0 + mB + mt*16 + grp;
        #pragma unroll
        for (int n2 = 0; n2 < 4; n2++) {
            int col = j0 + nB + n2*8 + 2*qid;
            *(float2*)(X + (size_t)row*NN + col)     = make_float2(c[mt][n2][0], c[mt][n2][1]);
            *(float2*)(X + (size_t)(row+8)*NN + col) = make_float2(c[mt][n2][2], c[mt][n2][3]);
        }
    }
}

// ---------------------------------------------------------------------------
// out: gather-transpose (MLP=8) + LN over H (4-wide ILP) + GEMM vs w_z with
// register double-buffered weight staging.
// smem: xt[128][132] + ws[128][36]  = 86016 B
// ---------------------------------------------------------------------------
__global__ __launch_bounds__(256)
void out_kernel(const float* __restrict__ lnw,
                const float* __restrict__ lnb,
                const float* __restrict__ w_z,
                float* __restrict__ out_x) {
    extern __shared__ float xs[];
    float* xt = xs;                // [128 px][132]
    float* ws = xs + 128*132;      // [128 d][36] per chunk
    int tid = threadIdx.x, warp = tid >> 5, lane = tid & 31;
    int grp = lane >> 2, qid = lane & 3;
    int p0 = blockIdx.x * 128;

    // gather transpose with 8 outstanding loads per batch
    {
        int cpx = tid & 127, hh0 = tid >> 7;
        const float* src = g_x + p0 + cpx;
        #pragma unroll
        for (int hb = 0; hb < 128; hb += 16) {
            float tmp[8];
            #pragma unroll
            for (int k = 0; k < 8; k++)
                tmp[k] = src[(size_t)(hb + 2*k + hh0)*NP];
            #pragma unroll
            for (int k = 0; k < 8; k++)
                xt[cpx*132 + hb + 2*k + hh0] = tmp[k];
        }
    }
    __syncthreads();

    // LN over h: 4 pixels per batch (4 independent shuffle chains)
    {
        float4 wv  = ((const float4*)lnw)[lane];
        float4 bvv = ((const float4*)lnb)[lane];
        #pragma unroll
        for (int pb = 0; pb < 16; pb += 4) {
            float4 v[4]; float s[4], sq[4];
            #pragma unroll
            for (int u = 0; u < 4; u++) {
                v[u] = *(float4*)(xt + (warp*16 + pb + u)*132 + lane*4);
                s[u]  = v[u].x + v[u].y + v[u].z + v[u].w;
                sq[u] = v[u].x*v[u].x + v[u].y*v[u].y + v[u].z*v[u].z + v[u].w*v[u].w;
            }
            #pragma unroll
            for (int o = 16; o > 0; o >>= 1) {
                #pragma unroll
                for (int u = 0; u < 4; u++) {
                    s[u]  += __shfl_xor_sync(0xffffffffu, s[u],  o);
                    sq[u] += __shfl_xor_sync(0xffffffffu, sq[u], o);
                }
            }
            #pragma unroll
            for (int u = 0; u < 4; u++) {
                float mean = s[u] * (1.0f/128.0f);
                float var  = sq[u] * (1.0f/128.0f) - mean*mean;
                float rs   = rsqrtf(var + 1e-5f);
                float* d = xt + (warp*16 + pb + u)*132 + lane*4;
                d[0] = tf32f((v[u].x-mean)*rs*wv.x + bvv.x);
                d[1] = tf32f((v[u].y-mean)*rs*wv.y + bvv.y);
                d[2] = tf32f((v[u].z-mean)*rs*wv.z + bvv.z);
                d[3] = tf32f((v[u].w-mean)*rs*wv.w + bvv.w);
            }
        }
    }
    __syncthreads();

    int wm = warp >> 2, wn = warp & 3;
    int mB = wm*64, nB = wn*32;
    float c[4][4][4];
    #pragma unroll
    for (int a = 0; a < 4; a++)
        #pragma unroll
        for (int b = 0; b < 4; b++)
            #pragma unroll
            for (int d = 0; d < 4; d++) c[a][b][d] = 0.f;

    int r = tid >> 3, cc = (tid & 7) << 2;
    // register double-buffer for w_z chunks
    float4 wreg[4];
    #pragma unroll
    for (int k = 0; k < 4; k++)
        wreg[k] = *(const float4*)(w_z + (r + k*32)*DD + cc);

    for (int kc = 0; kc < 4; kc++) {
        #pragma unroll
        for (int k = 0; k < 4; k++) {
            float4 v = wreg[k];
            float* pw = ws + (r + k*32)*36 + cc;
            pw[0]=tf32f(v.x); pw[1]=tf32f(v.y); pw[2]=tf32f(v.z); pw[3]=tf32f(v.w);
        }
        __syncthreads();
        if (kc + 1 < 4) {
            #pragma unroll
            for (int k = 0; k < 4; k++)
                wreg[k] = *(const float4*)(w_z + (r + k*32)*DD + (kc+1)*32 + cc);
        }
        #pragma unroll
        for (int ks = 0; ks < 4; ks++) {
            int k0w = ks*8;
            int k0a = kc*32 + ks*8;
            uint32_t bf[4][2];
            #pragma unroll
            for (int n2 = 0; n2 < 4; n2++) {
                int rowb = (nB + n2*8 + grp)*36 + k0w + qid;
                bf[n2][0] = __float_as_uint(ws[rowb]);
                bf[n2][1] = __float_as_uint(ws[rowb + 4]);
            }
            #pragma unroll
            for (int mt = 0; mt < 4; mt++) {
                int rowa = (mB + mt*16 + grp)*132 + k0a + qid;
                uint32_t a0 = __float_as_uint(xt[rowa]);
                uint32_t a1 = __float_as_uint(xt[rowa + 8*132]);
                uint32_t a2 = __float_as_uint(xt[rowa + 4]);
                uint32_t a3 = __float_as_uint(xt[rowa + 8*132 + 4]);
                #pragma unroll
                for (int n2 = 0; n2 < 4; n2++)
                    mma8(c[mt][n2], a0, a1, a2, a3, bf[n2][0], bf[n2][1]);
            }
        }
        __syncthreads();
    }
    #pragma unroll
    for (int mt = 0; mt < 4; mt++) {
        int p = p0 + mB + mt*16 + grp;
        #pragma unroll
        for (int n2 = 0; n2 < 4; n2++) {
            int d = nB + n2*8 + 2*qid;
            *(float2*)(out_x + (size_t)p*DD + d)     = make_float2(c[mt][n2][0], c[mt][n2][1]);
            *(float2*)(out_x + (size_t)(p+8)*DD + d) = make_float2(c[mt][n2][2], c[mt][n2][3]);
        }
    }
}

// ---------------------------------------------------------------------------
extern "C" void kernel_launch(void* const* d_in, const int* in_sizes, int n_in,
                              void* d_out, int out_size) {
    const float* z       = (const float*)d_in[0];
    const float* mask    = (const float*)d_in[1];
    const float* ln_in_w = (const float*)d_in[2];
    const float* ln_in_b = (const float*)d_in[3];
    const float* w_ab_p  = (const float*)d_in[4];
    const float* b_ab_p  = (const float*)d_in[5];
    const float* w_ab_g  = (const float*)d_in[6];
    const float* b_ab_g  = (const float*)d_in[7];
    const float* w_g     = (const float*)d_in[8];
    const float* ln_out_w= (const float*)d_in[9];
    const float* ln_out_b= (const float*)d_in[10];
    const float* w_z     = (const float*)d_in[11];

    float* out_x = (float*)d_out;
    float* out_g = (out_size >= 2*NP*DD) ? (out_x + (size_t)NP*DD) : nullptr;

    const int projSmem = (64*132 + 3*128*36 + 64*68) * 4;   // 106496
    const int triSmem  = 3 * 2 * 128*36 * 4;                // 110592
    const int outSmem  = (128*132 + 128*36) * 4;            // 86016
    cudaFuncSetAttribute(proj_kernel, cudaFuncAttributeMaxDynamicSharedMemorySize, projSmem);
    cudaFuncSetAttribute(tri_kernel,  cudaFuncAttributeMaxDynamicSharedMemorySize, triSmem);
    cudaFuncSetAttribute(out_kernel,  cudaFuncAttributeMaxDynamicSharedMemorySize, outSmem);

    prep_w<<<320, 256>>>(w_g, w_ab_p, w_ab_g);
    proj_kernel<<<NP/64, 256, projSmem>>>(z, ln_in_w, ln_in_b, mask, b_ab_p, b_ab_g, out_g);
    tri_kernel<<<dim3(16, 128), 256, triSmem>>>();
    out_kernel<<<NP/128, 256, outSmem>>>(ln_out_w, ln_out_b, w_z, out_x);
}

// round 11
// speedup vs baseline: 3.0869x; 1.0040x over previous
#include <cuda_runtime.h>
#include <cstdint>
#include <math.h>

#define NN 512
#define DD 128
#define NP (NN*NN)

__device__ float g_a [(size_t)DD*NP];   // a, tf32-rounded, head-major [h][i*N+k]
__device__ float g_b [(size_t)DD*NP];   // b, tf32-rounded, head-major [h][j*N+k]
__device__ float g_x [(size_t)DD*NP];   // triangle result f32, head-major
__device__ float g_w [640*DD];          // virtual weight matrix, tf32-rounded

// ---------------------------------------------------------------------------
__device__ __forceinline__ float tf32f(float f){
    uint32_t u; asm("cvt.rna.tf32.f32 %0, %1;" : "=r"(u) : "f"(f));
    return __uint_as_float(u);
}
__device__ __forceinline__ void mma8(float c[4], uint32_t a0, uint32_t a1,
                                     uint32_t a2, uint32_t a3,
                                     uint32_t b0, uint32_t b1){
    asm volatile(
        "mma.sync.aligned.m16n8k8.row.col.f32.tf32.tf32.f32 "
        "{%0,%1,%2,%3}, {%4,%5,%6,%7}, {%8,%9}, {%0,%1,%2,%3};"
        : "+f"(c[0]), "+f"(c[1]), "+f"(c[2]), "+f"(c[3])
        : "r"(a0), "r"(a1), "r"(a2), "r"(a3), "r"(b0), "r"(b1));
}
__device__ __forceinline__ uint32_t smem_u32(const void* p){
    uint32_t a;
    asm("{ .reg .u64 t; cvta.to.shared.u64 t, %1; cvt.u32.u64 %0, t; }" : "=r"(a) : "l"(p));
    return a;
}
__device__ __forceinline__ void cp16(uint32_t dst, const float* src){
    asm volatile("cp.async.cg.shared.global [%0], [%1], 16;" :: "r"(dst), "l"(src) : "memory");
}
#define CP_COMMIT() asm volatile("cp.async.commit_group;" ::: "memory")
#define CP_WAIT0()  asm volatile("cp.async.wait_group 0;" ::: "memory")
#define CP_WAIT1()  asm volatile("cp.async.wait_group 1;" ::: "memory")

// ---------------------------------------------------------------------------
__global__ void prep_w(const float* __restrict__ wg,
                       const float* __restrict__ wap,
                       const float* __restrict__ wag){
    int idx = blockIdx.x*256 + threadIdx.x;      // 81920 total
    int row = idx >> 7, col = idx & 127;
    const float* src;
    if (row < 128) src = wg + row*DD;
    else { int t = (row-128)>>1; src = (row & 1) ? (wag + t*DD) : (wap + t*DD); }
    g_w[idx] = tf32f(src[col]);
}

// ---------------------------------------------------------------------------
// proj: 64 pixels/CTA, fused LN, 20 W chunks via 3-stage ring, 1 barrier/chunk,
// ks-pipelined fragments, mask hoisted.
// smem: A[64][132] | W 3x[128][36] | stage[64][68]  = 106496 B  (2 CTA/SM)
// ---------------------------------------------------------------------------
__global__ __launch_bounds__(256)
void proj_kernel(const float* __restrict__ z,
                 const float* __restrict__ lnw, const float* __restrict__ lnb,
                 const float* __restrict__ mask,
                 const float* __restrict__ b_ab_p, const float* __restrict__ b_ab_g,
                 float* __restrict__ out_g) {
    extern __shared__ float sh[];
    float* As    = sh;                    // [64][132]
    float* Wb    = sh + 64*132;           // 3 x [128][36]
    float* stage = Wb + 3*128*36;         // [64][68]
    const int tid = threadIdx.x, warp = tid>>5, lane = tid&31;
    const int grp = lane>>2, qid = lane&3;
    const int wm = warp>>2, wn = warp&3;  // 2 x 4 warps
    const int mB = wm*32, nB = wn*32;
    const int pBase = blockIdx.x*64;
    uint32_t sW = smem_u32(Wb);

    // prefetch W chunks 0 and 1
    #pragma unroll
    for (int t = 0; t < 4; t++){
        int idx = tid + t*256, r = idx >> 3, seg = idx & 7;
        cp16(sW + (uint32_t)(r*144 + seg*16), g_w + (size_t)r*DD + seg*4);
    }
    CP_COMMIT();
    #pragma unroll
    for (int t = 0; t < 4; t++){
        int idx = tid + t*256, r = idx >> 3, seg = idx & 7;
        cp16(sW + (uint32_t)(18432 + r*144 + seg*16), g_w + (size_t)r*DD + 32 + seg*4);
    }
    CP_COMMIT();

    // hoisted mask values (nt-invariant)
    const float msc = 0.044194173824159216f;
    float mv0[2], mv1[2];
    #pragma unroll
    for (int mt = 0; mt < 2; mt++) {
        mv0[mt] = mask[pBase + mB + mt*16 + grp] * msc;
        mv1[mt] = mask[pBase + mB + mt*16 + grp + 8] * msc;
    }

    // fused input LayerNorm — 8 LDGs in flight, interleaved chains
    {
        float4 wv = ((const float4*)lnw)[lane];
        float4 bv = ((const float4*)lnb)[lane];
        float4 vv[8];
        #pragma unroll
        for (int it = 0; it < 8; it++)
            vv[it] = ((const float4*)(z + (size_t)(pBase + it*8 + warp)*DD))[lane];
        float s[8], sq[8];
        #pragma unroll
        for (int it = 0; it < 8; it++) {
            float4 v = vv[it];
            s[it]  = v.x + v.y + v.z + v.w;
            sq[it] = v.x*v.x + v.y*v.y + v.z*v.z + v.w*v.w;
        }
        #pragma unroll
        for (int o = 16; o > 0; o >>= 1) {
            #pragma unroll
            for (int it = 0; it < 8; it++) {
                s[it]  += __shfl_xor_sync(0xffffffffu, s[it],  o);
                sq[it] += __shfl_xor_sync(0xffffffffu, sq[it], o);
            }
        }
        #pragma unroll
        for (int it = 0; it < 8; it++) {
            float mean = s[it] * (1.0f/128.0f);
            float var  = sq[it] * (1.0f/128.0f) - mean*mean;
            float rs   = rsqrtf(var + 1e-5f);
            float4 v = vv[it];
            float* d = As + (it*8 + warp)*132 + lane*4;
            d[0] = tf32f((v.x-mean)*rs*wv.x + bv.x);
            d[1] = tf32f((v.y-mean)*rs*wv.y + bv.y);
            d[2] = tf32f((v.z-mean)*rs*wv.z + bv.z);
            d[3] = tf32f((v.w-mean)*rs*wv.w + bv.w);
        }
    }

    float c[2][4][4];
    for (int ci = 0; ci < 20; ci++) {
        if ((ci & 3) == 0) {
            #pragma unroll
            for (int a = 0; a < 2; a++)
                #pragma unroll
                for (int b = 0; b < 4; b++)
                    #pragma unroll
                    for (int d = 0; d < 4; d++) c[a][b][d] = 0.f;
        }
        if (ci == 19) CP_WAIT0(); else CP_WAIT1();
        __syncthreads();
        if (ci + 2 < 20) {
            int cj = ci + 2;
            uint32_t dst = sW + (uint32_t)((cj % 3) * 18432);
            const float* src = g_w + (size_t)(cj>>2)*128*DD + (cj&3)*32;
            #pragma unroll
            for (int t = 0; t < 4; t++){
                int idx = tid + t*256, r = idx >> 3, seg = idx & 7;
                cp16(dst + (uint32_t)(r*144 + seg*16), src + (size_t)r*DD + seg*4);
            }
            CP_COMMIT();
        }
        const float* Ws = Wb + (ci % 3) * 4608;
        // ks-pipelined fragment loop
        uint32_t bf[2][4][2], af[2][2][4];
        {   // preload ks=0
            int k0a = (ci&3)*32 + qid;
            #pragma unroll
            for (int n2 = 0; n2 < 4; n2++) {
                int rowb = (nB + n2*8 + grp)*36 + qid;
                bf[0][n2][0] = __float_as_uint(Ws[rowb]);
                bf[0][n2][1] = __float_as_uint(Ws[rowb + 4]);
            }
            #pragma unroll
            for (int mt = 0; mt < 2; mt++) {
                int rowa = (mB + mt*16 + grp)*132 + k0a;
                af[0][mt][0] = __float_as_uint(As[rowa]);
                af[0][mt][1] = __float_as_uint(As[rowa + 8*132]);
                af[0][mt][2] = __float_as_uint(As[rowa + 4]);
                af[0][mt][3] = __float_as_uint(As[rowa + 8*132 + 4]);
            }
        }
        #pragma unroll
        for (int ks = 0; ks < 4; ks++) {
            int cur = ks & 1, nxt = cur ^ 1;
            if (ks < 3) {
                int k0w = (ks+1)*8, k0a = (ci&3)*32 + k0w + qid;
                #pragma unroll
                for (int n2 = 0; n2 < 4; n2++) {
                    int rowb = (nB + n2*8 + grp)*36 + k0w + qid;
                    bf[nxt][n2][0] = __float_as_uint(Ws[rowb]);
                    bf[nxt][n2][1] = __float_as_uint(Ws[rowb + 4]);
                }
                #pragma unroll
                for (int mt = 0; mt < 2; mt++) {
                    int rowa = (mB + mt*16 + grp)*132 + k0a;
                    af[nxt][mt][0] = __float_as_uint(As[rowa]);
                    af[nxt][mt][1] = __float_as_uint(As[rowa + 8*132]);
                    af[nxt][mt][2] = __float_as_uint(As[rowa + 4]);
                    af[nxt][mt][3] = __float_as_uint(As[rowa + 8*132 + 4]);
                }
            }
            #pragma unroll
            for (int mt = 0; mt < 2; mt++)
                #pragma unroll
                for (int n2 = 0; n2 < 4; n2++)
                    mma8(c[mt][n2], af[cur][mt][0], af[cur][mt][1],
                         af[cur][mt][2], af[cur][mt][3],
                         bf[cur][n2][0], bf[cur][n2][1]);
        }
        if ((ci & 3) == 3) {
            int nt = ci >> 2;
            if (nt == 0) {
                if (out_g != nullptr) {
                    #pragma unroll
                    for (int mt = 0; mt < 2; mt++) {
                        int p = pBase + mB + mt*16 + grp;
                        #pragma unroll
                        for (int n2 = 0; n2 < 4; n2++) {
                            int O = nB + n2*8 + 2*qid;
                            *(float2*)(out_g + (size_t)p*DD + O)     = make_float2(c[mt][n2][0], c[mt][n2][1]);
                            *(float2*)(out_g + (size_t)(p+8)*DD + O) = make_float2(c[mt][n2][2], c[mt][n2][3]);
                        }
                    }
                }
            } else {
                int tB = (nt-1)*64;
                #pragma unroll
                for (int mt = 0; mt < 2; mt++) {
                    int px = mB + mt*16 + grp;
                    #pragma unroll
                    for (int n2 = 0; n2 < 4; n2++) {
                        int tl = wn*16 + n2*4 + qid;
                        float bp = b_ab_p[tB + tl];
                        float bg = b_ab_g[tB + tl];
                        float v0 = tf32f((c[mt][n2][0] + bp) * mv0[mt] *
                                         (1.0f/(1.0f + __expf(-(c[mt][n2][1] + bg)))));
                        float v1 = tf32f((c[mt][n2][2] + bp) * mv1[mt] *
                                         (1.0f/(1.0f + __expf(-(c[mt][n2][3] + bg)))));
                        stage[tl*68 + px]     = v0;
                        stage[tl*68 + px + 8] = v1;
                    }
                }
                __syncthreads();
                float* dstM = (tB < 128) ? g_a : g_b;
                int rowB = tB & 127;
                #pragma unroll
                for (int k = 0; k < 4; k++) {
                    int idx = tid + k*256, rr = idx >> 4, c4 = (idx & 15)*4;
                    *(float4*)(dstM + (size_t)(rowB + rr)*NP + pBase + c4) =
                        *(const float4*)(stage + rr*68 + c4);
                }
            }
        }
    }
}

// ---------------------------------------------------------------------------
// tri: X_h = A_h · B_h^T, 128x128 tile, 16 chunks of 32, 3-stage ring,
// 1 barrier/chunk, ks-pipelined fragments.
// smem: 3 x (A[128][36] + B[128][36]) = 110592 B
// ---------------------------------------------------------------------------
__global__ __launch_bounds__(256)
void tri_kernel() {
    extern __shared__ float sh[];
    const int tid = threadIdx.x, warp = tid>>5, lane = tid&31;
    const int grp = lane>>2, qid = lane&3;
    const int wm = warp>>2, wn = warp&3;
    const int mB = wm*64, nB = wn*32;
    int h  = blockIdx.y;
    int i0 = (blockIdx.x >> 2) * 128;
    int j0 = (blockIdx.x & 3) * 128;
    const float* A = g_a + (size_t)h*NP + (size_t)i0*NN;
    const float* B = g_b + (size_t)h*NP + (size_t)j0*NN;
    uint32_t s0 = smem_u32(sh);

    #pragma unroll
    for (int t = 0; t < 4; t++){
        int idx = tid + t*256, r = idx >> 3, seg = idx & 7;
        cp16(s0 + (uint32_t)(r*144 + seg*16),         A + (size_t)r*NN + seg*4);
        cp16(s0 + (uint32_t)(18432 + r*144 + seg*16), B + (size_t)r*NN + seg*4);
    }
    CP_COMMIT();
    #pragma unroll
    for (int t = 0; t < 4; t++){
        int idx = tid + t*256, r = idx >> 3, seg = idx & 7;
        cp16(s0 + (uint32_t)(36864 + r*144 + seg*16),         A + (size_t)r*NN + 32 + seg*4);
        cp16(s0 + (uint32_t)(36864 + 18432 + r*144 + seg*16), B + (size_t)r*NN + 32 + seg*4);
    }
    CP_COMMIT();

    float c[4][4][4];
    #pragma unroll
    for (int a = 0; a < 4; a++)
        #pragma unroll
        for (int b = 0; b < 4; b++)
            #pragma unroll
            for (int d = 0; d < 4; d++) c[a][b][d] = 0.f;

    for (int kc = 0; kc < 16; kc++) {
        if (kc == 15) CP_WAIT0(); else CP_WAIT1();
        __syncthreads();
        if (kc + 2 < 16) {
            int cj = kc + 2;
            uint32_t dst = s0 + (uint32_t)((cj % 3) * 36864);
            const float* As_ = A + cj*32;
            const float* Bs_ = B + cj*32;
            #pragma unroll
            for (int t = 0; t < 4; t++){
                int idx = tid + t*256, r = idx >> 3, seg = idx & 7;
                cp16(dst + (uint32_t)(r*144 + seg*16),         As_ + (size_t)r*NN + seg*4);
                cp16(dst + (uint32_t)(18432 + r*144 + seg*16), Bs_ + (size_t)r*NN + seg*4);
            }
            CP_COMMIT();
        }
        const float* Asm = sh + (kc % 3) * 9216;
        const float* Bsm = Asm + 4608;
        uint32_t bf[2][4][2], af[2][4][4];
        {
            #pragma unroll
            for (int n2 = 0; n2 < 4; n2++) {
                int rowb = (nB + n2*8 + grp)*36 + qid;
                bf[0][n2][0] = __float_as_uint(Bsm[rowb]);
                bf[0][n2][1] = __float_as_uint(Bsm[rowb + 4]);
            }
            #pragma unroll
            for (int mt = 0; mt < 4; mt++) {
                int rowa = (mB + mt*16 + grp)*36 + qid;
                af[0][mt][0] = __float_as_uint(Asm[rowa]);
                af[0][mt][1] = __float_as_uint(Asm[rowa + 8*36]);
                af[0][mt][2] = __float_as_uint(Asm[rowa + 4]);
                af[0][mt][3] = __float_as_uint(Asm[rowa + 8*36 + 4]);
            }
        }
        #pragma unroll
        for (int ks = 0; ks < 4; ks++) {
            int cur = ks & 1, nxt = cur ^ 1;
            if (ks < 3) {
                int k0 = (ks+1)*8;
                #pragma unroll
                for (int n2 = 0; n2 < 4; n2++) {
                    int rowb = (nB + n2*8 + grp)*36 + k0 + qid;
                    bf[nxt][n2][0] = __float_as_uint(Bsm[rowb]);
                    bf[nxt][n2][1] = __float_as_uint(Bsm[rowb + 4]);
                }
                #pragma unroll
                for (int mt = 0; mt < 4; mt++) {
                    int rowa = (mB + mt*16 + grp)*36 + k0 + qid;
                    af[nxt][mt][0] = __float_as_uint(Asm[rowa]);
                    af[nxt][mt][1] = __float_as_uint(Asm[rowa + 8*36]);
                    af[nxt][mt][2] = __float_as_uint(Asm[rowa + 4]);
                    af[nxt][mt][3] = __float_as_uint(Asm[rowa + 8*36 + 4]);
                }
            }
            #pragma unroll
            for (int mt = 0; mt < 4; mt++)
                #pragma unroll
                for (int n2 = 0; n2 < 4; n2++)
                    mma8(c[mt][n2], af[cur][mt][0], af[cur][mt][1],
                         af[cur][mt][2], af[cur][mt][3],
                         bf[cur][n2][0], bf[cur][n2][1]);
        }
    }
    float* X = g_x + (size_t)h*NP;
    #pragma unroll
    for (int mt = 0; mt < 4; mt++) {
        int row = i0 + mB + mt*16 + grp;
        #pragma unroll
        for (int n2 = 0; n2 < 4; n2++) {
            int col = j0 + nB + n2*8 + 2*qid;
            *(float2*)(X + (size_t)row*NN + col)     = make_float2(c[mt][n2][0], c[mt][n2][1]);
            *(float2*)(X + (size_t)(row+8)*NN + col) = make_float2(c[mt][n2][2], c[mt][n2][3]);
        }
    }
}

// ---------------------------------------------------------------------------
// out: gather-transpose (MLP=16) + LN over H (4-wide) + GEMM vs w_z
// (register-double-buffered weights, ks-pipelined fragments).
// smem: xt[128][132] + ws[128][36]  = 86016 B
// ---------------------------------------------------------------------------
__global__ __launch_bounds__(256)
void out_kernel(const float* __restrict__ lnw,
                const float* __restrict__ lnb,
                const float* __restrict__ w_z,
                float* __restrict__ out_x) {
    extern __shared__ float xs[];
    float* xt = xs;                // [128 px][132]
    float* ws = xs + 128*132;      // [128 d][36]
    int tid = threadIdx.x, warp = tid >> 5, lane = tid & 31;
    int grp = lane >> 2, qid = lane & 3;
    int p0 = blockIdx.x * 128;

    // gather transpose, 16 outstanding loads per batch
    {
        int cpx = tid & 127, hh0 = tid >> 7;
        const float* src = g_x + p0 + cpx;
        #pragma unroll
        for (int hb = 0; hb < 128; hb += 32) {
            float tmp[16];
            #pragma unroll
            for (int k = 0; k < 16; k++)
                tmp[k] = src[(size_t)(hb + 2*k + hh0)*NP];
            #pragma unroll
            for (int k = 0; k < 16; k++)
                xt[cpx*132 + hb + 2*k + hh0] = tmp[k];
        }
    }
    __syncthreads();

    {
        float4 wv  = ((const float4*)lnw)[lane];
        float4 bvv = ((const float4*)lnb)[lane];
        #pragma unroll
        for (int pb = 0; pb < 16; pb += 4) {
            float4 v[4]; float s[4], sq[4];
            #pragma unroll
            for (int u = 0; u < 4; u++) {
                v[u] = *(float4*)(xt + (warp*16 + pb + u)*132 + lane*4);
                s[u]  = v[u].x + v[u].y + v[u].z + v[u].w;
                sq[u] = v[u].x*v[u].x + v[u].y*v[u].y + v[u].z*v[u].z + v[u].w*v[u].w;
            }
            #pragma unroll
            for (int o = 16; o > 0; o >>= 1) {
                #pragma unroll
                for (int u = 0; u < 4; u++) {
                    s[u]  += __shfl_xor_sync(0xffffffffu, s[u],  o);
                    sq[u] += __shfl_xor_sync(0xffffffffu, sq[u], o);
                }
            }
            #pragma unroll
            for (int u = 0; u < 4; u++) {
                float mean = s[u] * (1.0f/128.0f);
                float var  = sq[u] * (1.0f/128.0f) - mean*mean;
                float rs   = rsqrtf(var + 1e-5f);
                float* d = xt + (warp*16 + pb + u)*132 + lane*4;
                d[0] = tf32f((v[u].x-mean)*rs*wv.x + bvv.x);
                d[1] = tf32f((v[u].y-mean)*rs*wv.y + bvv.y);
                d[2] = tf32f((v[u].z-mean)*rs*wv.z + bvv.z);
                d[3] = tf32f((v[u].w-mean)*rs*wv.w + bvv.w);
            }
        }
    }
    __syncthreads();

    int wm = warp >> 2, wn = warp & 3;
    int mB = wm*64, nB = wn*32;
    float c[4][4][4];
    #pragma unroll
    for (int a = 0; a < 4; a++)
        #pragma unroll
        for (int b = 0; b < 4; b++)
            #pragma unroll
            for (int d = 0; d < 4; d++) c[a][b][d] = 0.f;

    int r = tid >> 3, cc = (tid & 7) << 2;
    float4 wreg[4];
    #pragma unroll
    for (int k = 0; k < 4; k++)
        wreg[k] = *(const float4*)(w_z + (r + k*32)*DD + cc);

    for (int kc = 0; kc < 4; kc++) {
        #pragma unroll
        for (int k = 0; k < 4; k++) {
            float4 v = wreg[k];
            float* pw = ws + (r + k*32)*36 + cc;
            pw[0]=tf32f(v.x); pw[1]=tf32f(v.y); pw[2]=tf32f(v.z); pw[3]=tf32f(v.w);
        }
        __syncthreads();
        if (kc + 1 < 4) {
            #pragma unroll
            for (int k = 0; k < 4; k++)
                wreg[k] = *(const float4*)(w_z + (r + k*32)*DD + (kc+1)*32 + cc);
        }
        uint32_t bf[2][4][2], af[2][4][4];
        {
            int k0a = kc*32 + qid;
            #pragma unroll
            for (int n2 = 0; n2 < 4; n2++) {
                int rowb = (nB + n2*8 + grp)*36 + qid;
                bf[0][n2][0] = __float_as_uint(ws[rowb]);
                bf[0][n2][1] = __float_as_uint(ws[rowb + 4]);
            }
            #pragma unroll
            for (int mt = 0; mt < 4; mt++) {
                int rowa = (mB + mt*16 + grp)*132 + k0a;
                af[0][mt][0] = __float_as_uint(xt[rowa]);
                af[0][mt][1] = __float_as_uint(xt[rowa + 8*132]);
                af[0][mt][2] = __float_as_uint(xt[rowa + 4]);
                af[0][mt][3] = __float_as_uint(xt[rowa + 8*132 + 4]);
            }
        }
        #pragma unroll
        for (int ks = 0; ks < 4; ks++) {
            int cur = ks & 1, nxt = cur ^ 1;
            if (ks < 3) {
                int k0w = (ks+1)*8, k0a = kc*32 + k0w + qid;
                #pragma unroll
                for (int n2 = 0; n2 < 4; n2++) {
                    int rowb = (nB + n2*8 + grp)*36 + k0w + qid;
                    bf[nxt][n2][0] = __float_as_uint(ws[rowb]);
                    bf[nxt][n2][1] = __float_as_uint(ws[rowb + 4]);
                }
                #pragma unroll
                for (int mt = 0; mt < 4; mt++) {
                    int rowa = (mB + mt*16 + grp)*132 + k0a;
                    af[nxt][mt][0] = __float_as_uint(xt[rowa]);
                    af[nxt][mt][1] = __float_as_uint(xt[rowa + 8*132]);
                    af[nxt][mt][2] = __float_as_uint(xt[rowa + 4]);
                    af[nxt][mt][3] = __float_as_uint(xt[rowa + 8*132 + 4]);
                }
            }
            #pragma unroll
            for (int mt = 0; mt < 4; mt++)
                #pragma unroll
                for (int n2 = 0; n2 < 4; n2++)
                    mma8(c[mt][n2], af[cur][mt][0], af[cur][mt][1],
                         af[cur][mt][2], af[cur][mt][3],
                         bf[cur][n2][0], bf[cur][n2][1]);
        }
        __syncthreads();
    }
    #pragma unroll
    for (int mt = 0; mt < 4; mt++) {
        int p = p0 + mB + mt*16 + grp;
        #pragma unroll
        for (int n2 = 0; n2 < 4; n2++) {
            int d = nB + n2*8 + 2*qid;
            *(float2*)(out_x + (size_t)p*DD + d)     = make_float2(c[mt][n2][0], c[mt][n2][1]);
            *(float2*)(out_x + (size_t)(p+8)*DD + d) = make_float2(c[mt][n2][2], c[mt][n2][3]);
        }
    }
}

// ---------------------------------------------------------------------------
extern "C" void kernel_launch(void* const* d_in, const int* in_sizes, int n_in,
                              void* d_out, int out_size) {
    const float* z       = (const float*)d_in[0];
    const float* mask    = (const float*)d_in[1];
    const float* ln_in_w = (const float*)d_in[2];
    const float* ln_in_b = (const float*)d_in[3];
    const float* w_ab_p  = (const float*)d_in[4];
    const float* b_ab_p  = (const float*)d_in[5];
    const float* w_ab_g  = (const float*)d_in[6];
    const float* b_ab_g  = (const float*)d_in[7];
    const float* w_g     = (const float*)d_in[8];
    const float* ln_out_w= (const float*)d_in[9];
    const float* ln_out_b= (const float*)d_in[10];
    const float* w_z     = (const float*)d_in[11];

    float* out_x = (float*)d_out;
    float* out_g = (out_size >= 2*NP*DD) ? (out_x + (size_t)NP*DD) : nullptr;

    const int projSmem = (64*132 + 3*128*36 + 64*68) * 4;   // 106496
    const int triSmem  = 3 * 2 * 128*36 * 4;                // 110592
    const int outSmem  = (128*132 + 128*36) * 4;            // 86016
    cudaFuncSetAttribute(proj_kernel, cudaFuncAttributeMaxDynamicSharedMemorySize, projSmem);
    cudaFuncSetAttribute(tri_kernel,  cudaFuncAttributeMaxDynamicSharedMemorySize, triSmem);
    cudaFuncSetAttribute(out_kernel,  cudaFuncAttributeMaxDynamicSharedMemorySize, outSmem);

    prep_w<<<320, 256>>>(w_g, w_ab_p, w_ab_g);
    proj_kernel<<<NP/64, 256, projSmem>>>(z, ln_in_w, ln_in_b, mask, b_ab_p, b_ab_g, out_g);
    tri_kernel<<<dim3(16, 128), 256, triSmem>>>();
    out_kernel<<<NP/128, 256, outSmem>>>(ln_out_w, ln_out_b, w_z, out_x);
}

// round 12
// speedup vs baseline: 5.0096x; 1.6229x over previous
#include <cuda_runtime.h>
#include <cuda_fp16.h>
#include <cstdint>
#include <math.h>

#define NN 512
#define DD 128
#define NP (NN*NN)

__device__ __half g_a [(size_t)DD*NP];   // a, fp16, head-major [h][i*N+k]
__device__ __half g_b [(size_t)DD*NP];   // b, fp16, head-major [h][j*N+k]
__device__ __half g_x [(size_t)DD*NP];   // triangle result fp16, head-major
__device__ __half g_w [640*DD];          // virtual weight matrix fp16

// ---------------------------------------------------------------------------
__device__ __forceinline__ void mma16(float c[4], uint32_t a0, uint32_t a1,
                                      uint32_t a2, uint32_t a3,
                                      uint32_t b0, uint32_t b1){
    asm volatile(
        "mma.sync.aligned.m16n8k16.row.col.f32.f16.f16.f32 "
        "{%0,%1,%2,%3}, {%4,%5,%6,%7}, {%8,%9}, {%0,%1,%2,%3};"
        : "+f"(c[0]), "+f"(c[1]), "+f"(c[2]), "+f"(c[3])
        : "r"(a0), "r"(a1), "r"(a2), "r"(a3), "r"(b0), "r"(b1));
}
__device__ __forceinline__ uint32_t smem_u32(const void* p){
    uint32_t a;
    asm("{ .reg .u64 t; cvta.to.shared.u64 t, %1; cvt.u32.u64 %0, t; }" : "=r"(a) : "l"(p));
    return a;
}
__device__ __forceinline__ void cp16(uint32_t dst, const void* src){
    asm volatile("cp.async.cg.shared.global [%0], [%1], 16;" :: "r"(dst), "l"(src) : "memory");
}
#define CP_COMMIT() asm volatile("cp.async.commit_group;" ::: "memory")
#define CP_WAIT0()  asm volatile("cp.async.wait_group 0;" ::: "memory")
#define CP_WAIT1()  asm volatile("cp.async.wait_group 1;" ::: "memory")

// ---------------------------------------------------------------------------
// prep_w: fp16 virtual weight matrix. rows 0..127 = w_g ; 128+2t = w_ab_p[t] ;
// 129+2t = w_ab_g[t].
// ---------------------------------------------------------------------------
__global__ void prep_w(const float* __restrict__ wg,
                       const float* __restrict__ wap,
                       const float* __restrict__ wag){
    int idx = blockIdx.x*256 + threadIdx.x;      // 81920 total
    int row = idx >> 7, col = idx & 127;
    const float* src;
    if (row < 128) src = wg + row*DD;
    else { int t = (row-128)>>1; src = (row & 1) ? (wag + t*DD) : (wap + t*DD); }
    g_w[idx] = __float2half_rn(src[col]);
}

// ---------------------------------------------------------------------------
// proj: 64 pixels/CTA, fused LN, 20 W K-chunks (fp16) via 3-stage ring.
// smem (halves): A[64][136] | W 3x[128][40] | stage[64][72] = 57344 B
// ---------------------------------------------------------------------------
__global__ __launch_bounds__(256)
void proj_kernel(const float* __restrict__ z,
                 const float* __restrict__ lnw, const float* __restrict__ lnb,
                 const float* __restrict__ mask,
                 const float* __restrict__ b_ab_p, const float* __restrict__ b_ab_g,
                 float* __restrict__ out_g) {
    extern __shared__ char shc[];
    __half* As    = (__half*)shc;            // [64][136]
    __half* Wb    = As + 64*136;             // 3 x [128][40]
    __half* stage = Wb + 3*128*40;           // [64][72]
    const int tid = threadIdx.x, warp = tid>>5, lane = tid&31;
    const int grp = lane>>2, qid = lane&3;
    const int wm = warp>>2, wn = warp&3;     // 2 x 4 warps
    const int mB = wm*32, nB = wn*32;
    const int pBase = blockIdx.x*64;
    uint32_t sW = smem_u32(Wb);

    // prefetch W chunks 0,1 : each 128 rows x 32 halves (64B/row)
    #pragma unroll
    for (int t = 0; t < 2; t++){
        int idx = tid + t*256, r = idx >> 2, seg = idx & 3;
        cp16(sW + (uint32_t)(r*80 + seg*16), g_w + (size_t)r*DD + seg*8);
    }
    CP_COMMIT();
    #pragma unroll
    for (int t = 0; t < 2; t++){
        int idx = tid + t*256, r = idx >> 2, seg = idx & 3;
        cp16(sW + (uint32_t)(10240 + r*80 + seg*16), g_w + (size_t)r*DD + 32 + seg*8);
    }
    CP_COMMIT();

    // hoisted mask values
    const float msc = 0.044194173824159216f;
    float mv0[2], mv1[2];
    #pragma unroll
    for (int mt = 0; mt < 2; mt++) {
        mv0[mt] = mask[pBase + mB + mt*16 + grp] * msc;
        mv1[mt] = mask[pBase + mB + mt*16 + grp + 8] * msc;
    }

    // fused input LayerNorm (8 rows in flight) -> fp16 A tile
    {
        float4 wv = ((const float4*)lnw)[lane];
        float4 bv = ((const float4*)lnb)[lane];
        float4 vv[8];
        #pragma unroll
        for (int it = 0; it < 8; it++)
            vv[it] = ((const float4*)(z + (size_t)(pBase + it*8 + warp)*DD))[lane];
        float s[8], sq[8];
        #pragma unroll
        for (int it = 0; it < 8; it++) {
            float4 v = vv[it];
            s[it]  = v.x + v.y + v.z + v.w;
            sq[it] = v.x*v.x + v.y*v.y + v.z*v.z + v.w*v.w;
        }
        #pragma unroll
        for (int o = 16; o > 0; o >>= 1) {
            #pragma unroll
            for (int it = 0; it < 8; it++) {
                s[it]  += __shfl_xor_sync(0xffffffffu, s[it],  o);
                sq[it] += __shfl_xor_sync(0xffffffffu, sq[it], o);
            }
        }
        #pragma unroll
        for (int it = 0; it < 8; it++) {
            float mean = s[it] * (1.0f/128.0f);
            float var  = sq[it] * (1.0f/128.0f) - mean*mean;
            float rs   = rsqrtf(var + 1e-5f);
            float4 v = vv[it];
            __half* d = As + (it*8 + warp)*136 + lane*4;
            *(half2*)(d)     = __floats2half2_rn((v.x-mean)*rs*wv.x + bv.x,
                                                 (v.y-mean)*rs*wv.y + bv.y);
            *(half2*)(d + 2) = __floats2half2_rn((v.z-mean)*rs*wv.z + bv.z,
                                                 (v.w-mean)*rs*wv.w + bv.w);
        }
    }

    float c[2][4][4];
    for (int ci = 0; ci < 20; ci++) {
        if ((ci & 3) == 0) {
            #pragma unroll
            for (int a = 0; a < 2; a++)
                #pragma unroll
                for (int b = 0; b < 4; b++)
                    #pragma unroll
                    for (int d = 0; d < 4; d++) c[a][b][d] = 0.f;
        }
        if (ci == 19) CP_WAIT0(); else CP_WAIT1();
        __syncthreads();
        if (ci + 2 < 20) {
            int cj = ci + 2;
            uint32_t dst = sW + (uint32_t)((cj % 3) * 10240);
            const __half* src = g_w + (size_t)(cj>>2)*128*DD + (cj&3)*32;
            #pragma unroll
            for (int t = 0; t < 2; t++){
                int idx = tid + t*256, r = idx >> 2, seg = idx & 3;
                cp16(dst + (uint32_t)(r*80 + seg*16), src + (size_t)r*DD + seg*8);
            }
            CP_COMMIT();
        }
        const __half* Ws = Wb + (ci % 3) * 128*40;
        #pragma unroll
        for (int kk = 0; kk < 2; kk++) {
            int k0w = kk*16 + 2*qid;
            int k0a = (ci&3)*32 + kk*16 + 2*qid;
            uint32_t bf[4][2];
            #pragma unroll
            for (int n2 = 0; n2 < 4; n2++) {
                const __half* pb = Ws + (nB + n2*8 + grp)*40 + k0w;
                bf[n2][0] = *(const uint32_t*)(pb);
                bf[n2][1] = *(const uint32_t*)(pb + 8);
            }
            #pragma unroll
            for (int mt = 0; mt < 2; mt++) {
                const __half* pa = As + (mB + mt*16 + grp)*136 + k0a;
                uint32_t a0 = *(const uint32_t*)(pa);
                uint32_t a1 = *(const uint32_t*)(pa + 8*136);
                uint32_t a2 = *(const uint32_t*)(pa + 8);
                uint32_t a3 = *(const uint32_t*)(pa + 8*136 + 8);
                #pragma unroll
                for (int n2 = 0; n2 < 4; n2++)
                    mma16(c[mt][n2], a0, a1, a2, a3, bf[n2][0], bf[n2][1]);
            }
        }
        if ((ci & 3) == 3) {
            int nt = ci >> 2;
            if (nt == 0) {
                if (out_g != nullptr) {
                    #pragma unroll
                    for (int mt = 0; mt < 2; mt++) {
                        int p = pBase + mB + mt*16 + grp;
                        #pragma unroll
                        for (int n2 = 0; n2 < 4; n2++) {
                            int O = nB + n2*8 + 2*qid;
                            *(float2*)(out_g + (size_t)p*DD + O)     = make_float2(c[mt][n2][0], c[mt][n2][1]);
                            *(float2*)(out_g + (size_t)(p+8)*DD + O) = make_float2(c[mt][n2][2], c[mt][n2][3]);
                        }
                    }
                }
            } else {
                int tB = (nt-1)*64;
                #pragma unroll
                for (int mt = 0; mt < 2; mt++) {
                    int px = mB + mt*16 + grp;
                    #pragma unroll
                    for (int n2 = 0; n2 < 4; n2++) {
                        int tl = wn*16 + n2*4 + qid;
                        float bp = b_ab_p[tB + tl];
                        float bg = b_ab_g[tB + tl];
                        float v0 = (c[mt][n2][0] + bp) * mv0[mt] *
                                   (1.0f/(1.0f + __expf(-(c[mt][n2][1] + bg))));
                        float v1 = (c[mt][n2][2] + bp) * mv1[mt] *
                                   (1.0f/(1.0f + __expf(-(c[mt][n2][3] + bg))));
                        stage[tl*72 + px]     = __float2half_rn(v0);
                        stage[tl*72 + px + 8] = __float2half_rn(v1);
                    }
                }
                __syncthreads();
                __half* dstM = (tB < 128) ? g_a : g_b;
                int rowB = tB & 127;
                #pragma unroll
                for (int k = 0; k < 2; k++) {
                    int idx = tid + k*256, rr = idx >> 3, c8 = (idx & 7)*8;
                    *(float4*)(dstM + (size_t)(rowB + rr)*NP + pBase + c8) =
                        *(const float4*)(stage + rr*72 + c8);
                }
            }
        }
    }
}

// ---------------------------------------------------------------------------
// tri: X_h = A_h · B_h^T fp16, 128x128 C tile, K=512 in 16 chunks of 32,
// 3-stage ring, 1 barrier/chunk.
// smem: 3 x (A[128][40] + B[128][40]) halves = 61440 B
// ---------------------------------------------------------------------------
__global__ __launch_bounds__(256)
void tri_kernel() {
    extern __shared__ char shc[];
    __half* sh = (__half*)shc;
    const int tid = threadIdx.x, warp = tid>>5, lane = tid&31;
    const int grp = lane>>2, qid = lane&3;
    const int wm = warp>>2, wn = warp&3;
    const int mB = wm*64, nB = wn*32;
    int h  = blockIdx.y;
    int i0 = (blockIdx.x >> 2) * 128;
    int j0 = (blockIdx.x & 3) * 128;
    const __half* A = g_a + (size_t)h*NP + (size_t)i0*NN;
    const __half* B = g_b + (size_t)h*NP + (size_t)j0*NN;
    uint32_t s0 = smem_u32(sh);

    // prefetch chunks 0,1 (each: A and B 128 rows x 32 halves)
    #pragma unroll
    for (int t = 0; t < 2; t++){
        int idx = tid + t*256, r = idx >> 2, seg = idx & 3;
        cp16(s0 + (uint32_t)(r*80 + seg*16),          A + (size_t)r*NN + seg*8);
        cp16(s0 + (uint32_t)(10240 + r*80 + seg*16),  B + (size_t)r*NN + seg*8);
    }
    CP_COMMIT();
    #pragma unroll
    for (int t = 0; t < 2; t++){
        int idx = tid + t*256, r = idx >> 2, seg = idx & 3;
        cp16(s0 + (uint32_t)(20480 + r*80 + seg*16),          A + (size_t)r*NN + 32 + seg*8);
        cp16(s0 + (uint32_t)(20480 + 10240 + r*80 + seg*16),  B + (size_t)r*NN + 32 + seg*8);
    }
    CP_COMMIT();

    float c[4][4][4];
    #pragma unroll
    for (int a = 0; a < 4; a++)
        #pragma unroll
        for (int b = 0; b < 4; b++)
            #pragma unroll
            for (int d = 0; d < 4; d++) c[a][b][d] = 0.f;

    for (int kc = 0; kc < 16; kc++) {
        if (kc == 15) CP_WAIT0(); else CP_WAIT1();
        __syncthreads();
        if (kc + 2 < 16) {
            int cj = kc + 2;
            uint32_t dst = s0 + (uint32_t)((cj % 3) * 20480);
            const __half* As_ = A + cj*32;
            const __half* Bs_ = B + cj*32;
            #pragma unroll
            for (int t = 0; t < 2; t++){
                int idx = tid + t*256, r = idx >> 2, seg = idx & 3;
                cp16(dst + (uint32_t)(r*80 + seg*16),         As_ + (size_t)r*NN + seg*8);
                cp16(dst + (uint32_t)(10240 + r*80 + seg*16), Bs_ + (size_t)r*NN + seg*8);
            }
            CP_COMMIT();
        }
        const __half* Asm = sh + (kc % 3) * 10240;
        const __half* Bsm = Asm + 5120;
        #pragma unroll
        for (int kk = 0; kk < 2; kk++) {
            int k0 = kk*16 + 2*qid;
            uint32_t bf[4][2];
            #pragma unroll
            for (int n2 = 0; n2 < 4; n2++) {
                const __half* pb = Bsm + (nB + n2*8 + grp)*40 + k0;
                bf[n2][0] = *(const uint32_t*)(pb);
                bf[n2][1] = *(const uint32_t*)(pb + 8);
            }
            #pragma unroll
            for (int mt = 0; mt < 4; mt++) {
                const __half* pa = Asm + (mB + mt*16 + grp)*40 + k0;
                uint32_t a0 = *(const uint32_t*)(pa);
                uint32_t a1 = *(const uint32_t*)(pa + 8*40);
                uint32_t a2 = *(const uint32_t*)(pa + 8);
                uint32_t a3 = *(const uint32_t*)(pa + 8*40 + 8);
                #pragma unroll
                for (int n2 = 0; n2 < 4; n2++)
                    mma16(c[mt][n2], a0, a1, a2, a3, bf[n2][0], bf[n2][1]);
            }
        }
    }
    __half* X = g_x + (size_t)h*NP;
    #pragma unroll
    for (int mt = 0; mt < 4; mt++) {
        int row = i0 + mB + mt*16 + grp;
        #pragma unroll
        for (int n2 = 0; n2 < 4; n2++) {
            int col = j0 + nB + n2*8 + 2*qid;
            *(half2*)(X + (size_t)row*NN + col)     = __floats2half2_rn(c[mt][n2][0], c[mt][n2][1]);
            *(half2*)(X + (size_t)(row+8)*NN + col) = __floats2half2_rn(c[mt][n2][2], c[mt][n2][3]);
        }
    }
}

// ---------------------------------------------------------------------------
// out: gather-transpose (half, MLP=16) + LN over H + GEMM vs w_z (fp16 mma).
// smem (halves): xt[128][136] + ws[128][40] = 45056 B
// ---------------------------------------------------------------------------
__global__ __launch_bounds__(256)
void out_kernel(const float* __restrict__ lnw,
                const float* __restrict__ lnb,
                const float* __restrict__ w_z,
                float* __restrict__ out_x) {
    extern __shared__ char shc[];
    __half* xt = (__half*)shc;       // [128 px][136]
    __half* ws = xt + 128*136;       // [128 d][40]
    int tid = threadIdx.x, warp = tid >> 5, lane = tid & 31;
    int grp = lane >> 2, qid = lane & 3;
    int p0 = blockIdx.x * 128;

    // gather transpose, 16 outstanding half loads per batch
    {
        int cpx = tid & 127, hh0 = tid >> 7;
        const __half* src = g_x + p0 + cpx;
        #pragma unroll
        for (int hb = 0; hb < 128; hb += 32) {
            __half tmp[16];
            #pragma unroll
            for (int k = 0; k < 16; k++)
                tmp[k] = src[(size_t)(hb + 2*k + hh0)*NP];
            #pragma unroll
            for (int k = 0; k < 16; k++)
                xt[cpx*136 + hb + 2*k + hh0] = tmp[k];
        }
    }
    __syncthreads();

    // LN over h in f32, 4 pixels per batch, write back fp16
    {
        float4 wv  = ((const float4*)lnw)[lane];
        float4 bvv = ((const float4*)lnb)[lane];
        #pragma unroll
        for (int pb = 0; pb < 16; pb += 4) {
            float2 f0[4], f1[4]; float s[4], sq[4];
            #pragma unroll
            for (int u = 0; u < 4; u++) {
                __half* p = xt + (warp*16 + pb + u)*136 + lane*4;
                f0[u] = __half22float2(*(half2*)(p));
                f1[u] = __half22float2(*(half2*)(p + 2));
                s[u]  = f0[u].x + f0[u].y + f1[u].x + f1[u].y;
                sq[u] = f0[u].x*f0[u].x + f0[u].y*f0[u].y + f1[u].x*f1[u].x + f1[u].y*f1[u].y;
            }
            #pragma unroll
            for (int o = 16; o > 0; o >>= 1) {
                #pragma unroll
                for (int u = 0; u < 4; u++) {
                    s[u]  += __shfl_xor_sync(0xffffffffu, s[u],  o);
                    sq[u] += __shfl_xor_sync(0xffffffffu, sq[u], o);
                }
            }
            #pragma unroll
            for (int u = 0; u < 4; u++) {
                float mean = s[u] * (1.0f/128.0f);
                float var  = sq[u] * (1.0f/128.0f) - mean*mean;
                float rs   = rsqrtf(var + 1e-5f);
                __half* p = xt + (warp*16 + pb + u)*136 + lane*4;
                *(half2*)(p)     = __floats2half2_rn((f0[u].x-mean)*rs*wv.x + bvv.x,
                                                     (f0[u].y-mean)*rs*wv.y + bvv.y);
                *(half2*)(p + 2) = __floats2half2_rn((f1[u].x-mean)*rs*wv.z + bvv.z,
                                                     (f1[u].y-mean)*rs*wv.w + bvv.w);
            }
        }
    }
    __syncthreads();

    int wm = warp >> 2, wn = warp & 3;
    int mB = wm*64, nB = wn*32;
    float c[4][4][4];
    #pragma unroll
    for (int a = 0; a < 4; a++)
        #pragma unroll
        for (int b = 0; b < 4; b++)
            #pragma unroll
            for (int d = 0; d < 4; d++) c[a][b][d] = 0.f;

    int r = tid >> 3, cc = (tid & 7) << 2;
    float4 wreg[4];
    #pragma unroll
    for (int k = 0; k < 4; k++)
        wreg[k] = *(const float4*)(w_z + (r + k*32)*DD + cc);

    for (int kc = 0; kc < 4; kc++) {
        #pragma unroll
        for (int k = 0; k < 4; k++) {
            float4 v = wreg[k];
            __half* pw = ws + (r + k*32)*40 + cc;
            *(half2*)(pw)     = __floats2half2_rn(v.x, v.y);
            *(half2*)(pw + 2) = __floats2half2_rn(v.z, v.w);
        }
        __syncthreads();
        if (kc + 1 < 4) {
            #pragma unroll
            for (int k = 0; k < 4; k++)
                wreg[k] = *(const float4*)(w_z + (r + k*32)*DD + (kc+1)*32 + cc);
        }
        #pragma unroll
        for (int kk = 0; kk < 2; kk++) {
            int k0w = kk*16 + 2*qid;
            int k0a = kc*32 + kk*16 + 2*qid;
            uint32_t bf[4][2];
            #pragma unroll
            for (int n2 = 0; n2 < 4; n2++) {
                const __half* pb = ws + (nB + n2*8 + grp)*40 + k0w;
                bf[n2][0] = *(const uint32_t*)(pb);
                bf[n2][1] = *(const uint32_t*)(pb + 8);
            }
            #pragma unroll
            for (int mt = 0; mt < 4; mt++) {
                const __half* pa = xt + (mB + mt*16 + grp)*136 + k0a;
                uint32_t a0 = *(const uint32_t*)(pa);
                uint32_t a1 = *(const uint32_t*)(pa + 8*136);
                uint32_t a2 = *(const uint32_t*)(pa + 8);
                uint32_t a3 = *(const uint32_t*)(pa + 8*136 + 8);
                #pragma unroll
                for (int n2 = 0; n2 < 4; n2++)
                    mma16(c[mt][n2], a0, a1, a2, a3, bf[n2][0], bf[n2][1]);
            }
        }
        __syncthreads();
    }
    #pragma unroll
    for (int mt = 0; mt < 4; mt++) {
        int p = p0 + mB + mt*16 + grp;
        #pragma unroll
        for (int n2 = 0; n2 < 4; n2++) {
            int d = nB + n2*8 + 2*qid;
            *(float2*)(out_x + (size_t)p*DD + d)     = make_float2(c[mt][n2][0], c[mt][n2][1]);
            *(float2*)(out_x + (size_t)(p+8)*DD + d) = make_float2(c[mt][n2][2], c[mt][n2][3]);
        }
    }
}

// ---------------------------------------------------------------------------
extern "C" void kernel_launch(void* const* d_in, const int* in_sizes, int n_in,
                              void* d_out, int out_size) {
    const float* z       = (const float*)d_in[0];
    const float* mask    = (const float*)d_in[1];
    const float* ln_in_w = (const float*)d_in[2];
    const float* ln_in_b = (const float*)d_in[3];
    const float* w_ab_p  = (const float*)d_in[4];
    const float* b_ab_p  = (const float*)d_in[5];
    const float* w_ab_g  = (const float*)d_in[6];
    const float* b_ab_g  = (const float*)d_in[7];
    const float* w_g     = (const float*)d_in[8];
    const float* ln_out_w= (const float*)d_in[9];
    const float* ln_out_b= (const float*)d_in[10];
    const float* w_z     = (const float*)d_in[11];

    float* out_x = (float*)d_out;
    float* out_g = (out_size >= 2*NP*DD) ? (out_x + (size_t)NP*DD) : nullptr;

    const int projSmem = (64*136 + 3*128*40 + 64*72) * 2;   // 57344
    const int triSmem  = 3 * 2 * 128*40 * 2;                // 61440
    const int outSmem  = (128*136 + 128*40) * 2;            // 45056
    cudaFuncSetAttribute(proj_kernel, cudaFuncAttributeMaxDynamicSharedMemorySize, projSmem);
    cudaFuncSetAttribute(tri_kernel,  cudaFuncAttributeMaxDynamicSharedMemorySize, triSmem);
    cudaFuncSetAttribute(out_kernel,  cudaFuncAttributeMaxDynamicSharedMemorySize, outSmem);

    prep_w<<<320, 256>>>(w_g, w_ab_p, w_ab_g);
    proj_kernel<<<NP/64, 256, projSmem>>>(z, ln_in_w, ln_in_b, mask, b_ab_p, b_ab_g, out_g);
    tri_kernel<<<dim3(16, 128), 256, triSmem>>>();
    out_kernel<<<NP/128, 256, outSmem>>>(ln_out_w, ln_out_b, w_z, out_x);
}

// round 13
// speedup vs baseline: 5.0541x; 1.0089x over previous
#include <cuda_runtime.h>
#include <cuda_fp16.h>
#include <cstdint>
#include <math.h>

#define NN 512
#define DD 128
#define NP (NN*NN)

__device__ __half g_a [(size_t)DD*NP];   // a, fp16, head-major [h][i*N+k]
__device__ __half g_b [(size_t)DD*NP];   // b, fp16, head-major [h][j*N+k]
__device__ __half g_x [(size_t)DD*NP];   // triangle result fp16, head-major
__device__ __half g_w [640*DD];          // virtual weight matrix fp16

// ---------------------------------------------------------------------------
__device__ __forceinline__ void mma16(float c[4], uint32_t a0, uint32_t a1,
                                      uint32_t a2, uint32_t a3,
                                      uint32_t b0, uint32_t b1){
    asm volatile(
        "mma.sync.aligned.m16n8k16.row.col.f32.f16.f16.f32 "
        "{%0,%1,%2,%3}, {%4,%5,%6,%7}, {%8,%9}, {%0,%1,%2,%3};"
        : "+f"(c[0]), "+f"(c[1]), "+f"(c[2]), "+f"(c[3])
        : "r"(a0), "r"(a1), "r"(a2), "r"(a3), "r"(b0), "r"(b1));
}
__device__ __forceinline__ uint32_t smem_u32(const void* p){
    uint32_t a;
    asm("{ .reg .u64 t; cvta.to.shared.u64 t, %1; cvt.u32.u64 %0, t; }" : "=r"(a) : "l"(p));
    return a;
}
__device__ __forceinline__ void cp16(uint32_t dst, const void* src){
    asm volatile("cp.async.cg.shared.global [%0], [%1], 16;" :: "r"(dst), "l"(src) : "memory");
}
#define CP_COMMIT() asm volatile("cp.async.commit_group;" ::: "memory")
#define CP_WAIT0()  asm volatile("cp.async.wait_group 0;" ::: "memory")
#define CP_WAIT1()  asm volatile("cp.async.wait_group 1;" ::: "memory")

// ---------------------------------------------------------------------------
// prep_w: fp16 virtual weight matrix. rows 0..127 = w_g ; 128+2t = w_ab_p[t] ;
// 129+2t = w_ab_g[t].
// ---------------------------------------------------------------------------
__global__ void prep_w(const float* __restrict__ wg,
                       const float* __restrict__ wap,
                       const float* __restrict__ wag){
    int idx = blockIdx.x*256 + threadIdx.x;      // 81920 total
    int row = idx >> 7, col = idx & 127;
    const float* src;
    if (row < 128) src = wg + row*DD;
    else { int t = (row-128)>>1; src = (row & 1) ? (wag + t*DD) : (wap + t*DD); }
    g_w[idx] = __float2half_rn(src[col]);
}

// ---------------------------------------------------------------------------
// proj: 128 pixels/CTA, fused LN, 20 W K-chunks (fp16) via 3-stage ring.
// smem (halves): A[128][136] | W 3x[128][40] | stage[64][136] = 82944 B (2 CTA/SM)
// ---------------------------------------------------------------------------
__global__ __launch_bounds__(256, 2)
void proj_kernel(const float* __restrict__ z,
                 const float* __restrict__ lnw, const float* __restrict__ lnb,
                 const float* __restrict__ mask,
                 const float* __restrict__ b_ab_p, const float* __restrict__ b_ab_g,
                 float* __restrict__ out_g) {
    extern __shared__ char shc[];
    __half* As    = (__half*)shc;            // [128][136]
    __half* Wb    = As + 128*136;            // 3 x [128][40]
    __half* stage = Wb + 3*128*40;           // [64][136]
    const int tid = threadIdx.x, warp = tid>>5, lane = tid&31;
    const int grp = lane>>2, qid = lane&3;
    const int wm = warp>>2, wn = warp&3;     // 2 x 4 warps
    const int mB = wm*64, nB = wn*32;
    const int pBase = blockIdx.x*128;
    uint32_t sW = smem_u32(Wb);

    // prefetch W chunks 0,1 : each 128 rows x 32 halves (64B/row)
    #pragma unroll
    for (int t = 0; t < 2; t++){
        int idx = tid + t*256, r = idx >> 2, seg = idx & 3;
        cp16(sW + (uint32_t)(r*80 + seg*16), g_w + (size_t)r*DD + seg*8);
    }
    CP_COMMIT();
    #pragma unroll
    for (int t = 0; t < 2; t++){
        int idx = tid + t*256, r = idx >> 2, seg = idx & 3;
        cp16(sW + (uint32_t)(10240 + r*80 + seg*16), g_w + (size_t)r*DD + 32 + seg*8);
    }
    CP_COMMIT();

    // hoisted mask values (nt-invariant), 4 m-tiles
    const float msc = 0.044194173824159216f;
    float mv0[4], mv1[4];
    #pragma unroll
    for (int mt = 0; mt < 4; mt++) {
        mv0[mt] = mask[pBase + mB + mt*16 + grp] * msc;
        mv1[mt] = mask[pBase + mB + mt*16 + grp + 8] * msc;
    }

    // fused input LayerNorm -> fp16 A tile, two 8-row-deep batches
    {
        float4 wv = ((const float4*)lnw)[lane];
        float4 bv = ((const float4*)lnb)[lane];
        #pragma unroll
        for (int hB = 0; hB < 2; hB++) {
            float4 vv[8];
            #pragma unroll
            for (int it = 0; it < 8; it++)
                vv[it] = ((const float4*)(z + (size_t)(pBase + hB*64 + it*8 + warp)*DD))[lane];
            float s[8], sq[8];
            #pragma unroll
            for (int it = 0; it < 8; it++) {
                float4 v = vv[it];
                s[it]  = v.x + v.y + v.z + v.w;
                sq[it] = v.x*v.x + v.y*v.y + v.z*v.z + v.w*v.w;
            }
            #pragma unroll
            for (int o = 16; o > 0; o >>= 1) {
                #pragma unroll
                for (int it = 0; it < 8; it++) {
                    s[it]  += __shfl_xor_sync(0xffffffffu, s[it],  o);
                    sq[it] += __shfl_xor_sync(0xffffffffu, sq[it], o);
                }
            }
            #pragma unroll
            for (int it = 0; it < 8; it++) {
                float mean = s[it] * (1.0f/128.0f);
                float var  = sq[it] * (1.0f/128.0f) - mean*mean;
                float rs   = rsqrtf(var + 1e-5f);
                float4 v = vv[it];
                __half* d = As + (hB*64 + it*8 + warp)*136 + lane*4;
                *(half2*)(d)     = __floats2half2_rn((v.x-mean)*rs*wv.x + bv.x,
                                                     (v.y-mean)*rs*wv.y + bv.y);
                *(half2*)(d + 2) = __floats2half2_rn((v.z-mean)*rs*wv.z + bv.z,
                                                     (v.w-mean)*rs*wv.w + bv.w);
            }
        }
    }

    float c[4][4][4];
    for (int ci = 0; ci < 20; ci++) {
        if ((ci & 3) == 0) {
            #pragma unroll
            for (int a = 0; a < 4; a++)
                #pragma unroll
                for (int b = 0; b < 4; b++)
                    #pragma unroll
                    for (int d = 0; d < 4; d++) c[a][b][d] = 0.f;
        }
        if (ci == 19) CP_WAIT0(); else CP_WAIT1();
        __syncthreads();
        if (ci + 2 < 20) {
            int cj = ci + 2;
            uint32_t dst = sW + (uint32_t)((cj % 3) * 10240);
            const __half* src = g_w + (size_t)(cj>>2)*128*DD + (cj&3)*32;
            #pragma unroll
            for (int t = 0; t < 2; t++){
                int idx = tid + t*256, r = idx >> 2, seg = idx & 3;
                cp16(dst + (uint32_t)(r*80 + seg*16), src + (size_t)r*DD + seg*8);
            }
            CP_COMMIT();
        }
        const __half* Ws = Wb + (ci % 3) * 128*40;
        #pragma unroll
        for (int kk = 0; kk < 2; kk++) {
            int k0w = kk*16 + 2*qid;
            int k0a = (ci&3)*32 + kk*16 + 2*qid;
            uint32_t bf[4][2];
            #pragma unroll
            for (int n2 = 0; n2 < 4; n2++) {
                const __half* pb = Ws + (nB + n2*8 + grp)*40 + k0w;
                bf[n2][0] = *(const uint32_t*)(pb);
                bf[n2][1] = *(const uint32_t*)(pb + 8);
            }
            #pragma unroll
            for (int mt = 0; mt < 4; mt++) {
                const __half* pa = As + (mB + mt*16 + grp)*136 + k0a;
                uint32_t a0 = *(const uint32_t*)(pa);
                uint32_t a1 = *(const uint32_t*)(pa + 8*136);
                uint32_t a2 = *(const uint32_t*)(pa + 8);
                uint32_t a3 = *(const uint32_t*)(pa + 8*136 + 8);
                #pragma unroll
                for (int n2 = 0; n2 < 4; n2++)
                    mma16(c[mt][n2], a0, a1, a2, a3, bf[n2][0], bf[n2][1]);
            }
        }
        if ((ci & 3) == 3) {
            int nt = ci >> 2;
            if (nt == 0) {
                if (out_g != nullptr) {
                    #pragma unroll
                    for (int mt = 0; mt < 4; mt++) {
                        int p = pBase + mB + mt*16 + grp;
                        #pragma unroll
                        for (int n2 = 0; n2 < 4; n2++) {
                            int O = nB + n2*8 + 2*qid;
                            *(float2*)(out_g + (size_t)p*DD + O)     = make_float2(c[mt][n2][0], c[mt][n2][1]);
                            *(float2*)(out_g + (size_t)(p+8)*DD + O) = make_float2(c[mt][n2][2], c[mt][n2][3]);
                        }
                    }
                }
            } else {
                int tB = (nt-1)*64;
                #pragma unroll
                for (int mt = 0; mt < 4; mt++) {
                    int px = mB + mt*16 + grp;
                    #pragma unroll
                    for (int n2 = 0; n2 < 4; n2++) {
                        int tl = wn*16 + n2*4 + qid;
                        float bp = b_ab_p[tB + tl];
                        float bg = b_ab_g[tB + tl];
                        float v0 = (c[mt][n2][0] + bp) * mv0[mt] *
                                   (1.0f/(1.0f + __expf(-(c[mt][n2][1] + bg))));
                        float v1 = (c[mt][n2][2] + bp) * mv1[mt] *
                                   (1.0f/(1.0f + __expf(-(c[mt][n2][3] + bg))));
                        stage[tl*136 + px]     = __float2half_rn(v0);
                        stage[tl*136 + px + 8] = __float2half_rn(v1);
                    }
                }
                __syncthreads();
                __half* dstM = (tB < 128) ? g_a : g_b;
                int rowB = tB & 127;
                #pragma unroll
                for (int k = 0; k < 4; k++) {
                    int idx = tid + k*256, rr = idx >> 4, c8 = (idx & 15)*8;
                    *(float4*)(dstM + (size_t)(rowB + rr)*NP + pBase + c8) =
                        *(const float4*)(stage + rr*136 + c8);
                }
            }
        }
    }
}

// ---------------------------------------------------------------------------
// tri: X_h = A_h · B_h^T fp16, 128x128 C tile, K=512 in 16 chunks of 32,
// 3-stage ring, 1 barrier/chunk. (unchanged)
// smem: 3 x (A[128][40] + B[128][40]) halves = 61440 B
// ---------------------------------------------------------------------------
__global__ __launch_bounds__(256)
void tri_kernel() {
    extern __shared__ char shc[];
    __half* sh = (__half*)shc;
    const int tid = threadIdx.x, warp = tid>>5, lane = tid&31;
    const int grp = lane>>2, qid = lane&3;
    const int wm = warp>>2, wn = warp&3;
    const int mB = wm*64, nB = wn*32;
    int h  = blockIdx.y;
    int i0 = (blockIdx.x >> 2) * 128;
    int j0 = (blockIdx.x & 3) * 128;
    const __half* A = g_a + (size_t)h*NP + (size_t)i0*NN;
    const __half* B = g_b + (size_t)h*NP + (size_t)j0*NN;
    uint32_t s0 = smem_u32(sh);

    #pragma unroll
    for (int t = 0; t < 2; t++){
        int idx = tid + t*256, r = idx >> 2, seg = idx & 3;
        cp16(s0 + (uint32_t)(r*80 + seg*16),          A + (size_t)r*NN + seg*8);
        cp16(s0 + (uint32_t)(10240 + r*80 + seg*16),  B + (size_t)r*NN + seg*8);
    }
    CP_COMMIT();
    #pragma unroll
    for (int t = 0; t < 2; t++){
        int idx = tid + t*256, r = idx >> 2, seg = idx & 3;
        cp16(s0 + (uint32_t)(20480 + r*80 + seg*16),          A + (size_t)r*NN + 32 + seg*8);
        cp16(s0 + (uint32_t)(20480 + 10240 + r*80 + seg*16),  B + (size_t)r*NN + 32 + seg*8);
    }
    CP_COMMIT();

    float c[4][4][4];
    #pragma unroll
    for (int a = 0; a < 4; a++)
        #pragma unroll
        for (int b = 0; b < 4; b++)
            #pragma unroll
            for (int d = 0; d < 4; d++) c[a][b][d] = 0.f;

    for (int kc = 0; kc < 16; kc++) {
        if (kc == 15) CP_WAIT0(); else CP_WAIT1();
        __syncthreads();
        if (kc + 2 < 16) {
            int cj = kc + 2;
            uint32_t dst = s0 + (uint32_t)((cj % 3) * 20480);
            const __half* As_ = A + cj*32;
            const __half* Bs_ = B + cj*32;
            #pragma unroll
            for (int t = 0; t < 2; t++){
                int idx = tid + t*256, r = idx >> 2, seg = idx & 3;
                cp16(dst + (uint32_t)(r*80 + seg*16),         As_ + (size_t)r*NN + seg*8);
                cp16(dst + (uint32_t)(10240 + r*80 + seg*16), Bs_ + (size_t)r*NN + seg*8);
            }
            CP_COMMIT();
        }
        const __half* Asm = sh + (kc % 3) * 10240;
        const __half* Bsm = Asm + 5120;
        #pragma unroll
        for (int kk = 0; kk < 2; kk++) {
            int k0 = kk*16 + 2*qid;
            uint32_t bf[4][2];
            #pragma unroll
            for (int n2 = 0; n2 < 4; n2++) {
                const __half* pb = Bsm + (nB + n2*8 + grp)*40 + k0;
                bf[n2][0] = *(const uint32_t*)(pb);
                bf[n2][1] = *(const uint32_t*)(pb + 8);
            }
            #pragma unroll
            for (int mt = 0; mt < 4; mt++) {
                const __half* pa = Asm + (mB + mt*16 + grp)*40 + k0;
                uint32_t a0 = *(const uint32_t*)(pa);
                uint32_t a1 = *(const uint32_t*)(pa + 8*40);
                uint32_t a2 = *(const uint32_t*)(pa + 8);
                uint32_t a3 = *(const uint32_t*)(pa + 8*40 + 8);
                #pragma unroll
                for (int n2 = 0; n2 < 4; n2++)
                    mma16(c[mt][n2], a0, a1, a2, a3, bf[n2][0], bf[n2][1]);
            }
        }
    }
    __half* X = g_x + (size_t)h*NP;
    #pragma unroll
    for (int mt = 0; mt < 4; mt++) {
        int row = i0 + mB + mt*16 + grp;
        #pragma unroll
        for (int n2 = 0; n2 < 4; n2++) {
            int col = j0 + nB + n2*8 + 2*qid;
            *(half2*)(X + (size_t)row*NN + col)     = __floats2half2_rn(c[mt][n2][0], c[mt][n2][1]);
            *(half2*)(X + (size_t)(row+8)*NN + col) = __floats2half2_rn(c[mt][n2][2], c[mt][n2][3]);
        }
    }
}

// ---------------------------------------------------------------------------
// out: gather-transpose (half, MLP=16) + LN over H + GEMM vs w_z (fp16 mma).
// (unchanged)  smem (halves): xt[128][136] + ws[128][40] = 45056 B
// ---------------------------------------------------------------------------
__global__ __launch_bounds__(256)
void out_kernel(const float* __restrict__ lnw,
                const float* __restrict__ lnb,
                const float* __restrict__ w_z,
                float* __restrict__ out_x) {
    extern __shared__ char shc[];
    __half* xt = (__half*)shc;       // [128 px][136]
    __half* ws = xt + 128*136;       // [128 d][40]
    int tid = threadIdx.x, warp = tid >> 5, lane = tid & 31;
    int grp = lane >> 2, qid = lane & 3;
    int p0 = blockIdx.x * 128;

    {
        int cpx = tid & 127, hh0 = tid >> 7;
        const __half* src = g_x + p0 + cpx;
        #pragma unroll
        for (int hb = 0; hb < 128; hb += 32) {
            __half tmp[16];
            #pragma unroll
            for (int k = 0; k < 16; k++)
                tmp[k] = src[(size_t)(hb + 2*k + hh0)*NP];
            #pragma unroll
            for (int k = 0; k < 16; k++)
                xt[cpx*136 + hb + 2*k + hh0] = tmp[k];
        }
    }
    __syncthreads();

    {
        float4 wv  = ((const float4*)lnw)[lane];
        float4 bvv = ((const float4*)lnb)[lane];
        #pragma unroll
        for (int pb = 0; pb < 16; pb += 4) {
            float2 f0[4], f1[4]; float s[4], sq[4];
            #pragma unroll
            for (int u = 0; u < 4; u++) {
                __half* p = xt + (warp*16 + pb + u)*136 + lane*4;
                f0[u] = __half22float2(*(half2*)(p));
                f1[u] = __half22float2(*(half2*)(p + 2));
                s[u]  = f0[u].x + f0[u].y + f1[u].x + f1[u].y;
                sq[u] = f0[u].x*f0[u].x + f0[u].y*f0[u].y + f1[u].x*f1[u].x + f1[u].y*f1[u].y;
            }
            #pragma unroll
            for (int o = 16; o > 0; o >>= 1) {
                #pragma unroll
                for (int u = 0; u < 4; u++) {
                    s[u]  += __shfl_xor_sync(0xffffffffu, s[u],  o);
                    sq[u] += __shfl_xor_sync(0xffffffffu, sq[u], o);
                }
            }
            #pragma unroll
            for (int u = 0; u < 4; u++) {
                float mean = s[u] * (1.0f/128.0f);
                float var  = sq[u] * (1.0f/128.0f) - mean*mean;
                float rs   = rsqrtf(var + 1e-5f);
                __half* p = xt + (warp*16 + pb + u)*136 + lane*4;
                *(half2*)(p)     = __floats2half2_rn((f0[u].x-mean)*rs*wv.x + bvv.x,
                                                     (f0[u].y-mean)*rs*wv.y + bvv.y);
                *(half2*)(p + 2) = __floats2half2_rn((f1[u].x-mean)*rs*wv.z + bvv.z,
                                                     (f1[u].y-mean)*rs*wv.w + bvv.w);
            }
        }
    }
    __syncthreads();

    int wm = warp >> 2, wn = warp & 3;
    int mB = wm*64, nB = wn*32;
    float c[4][4][4];
    #pragma unroll
    for (int a = 0; a < 4; a++)
        #pragma unroll
        for (int b = 0; b < 4; b++)
            #pragma unroll
            for (int d = 0; d < 4; d++) c[a][b][d] = 0.f;

    int r = tid >> 3, cc = (tid & 7) << 2;
    float4 wreg[4];
    #pragma unroll
    for (int k = 0; k < 4; k++)
        wreg[k] = *(const float4*)(w_z + (r + k*32)*DD + cc);

    for (int kc = 0; kc < 4; kc++) {
        #pragma unroll
        for (int k = 0; k < 4; k++) {
            float4 v = wreg[k];
            __half* pw = ws + (r + k*32)*40 + cc;
            *(half2*)(pw)     = __floats2half2_rn(v.x, v.y);
            *(half2*)(pw + 2) = __floats2half2_rn(v.z, v.w);
        }
        __syncthreads();
        if (kc + 1 < 4) {
            #pragma unroll
            for (int k = 0; k < 4; k++)
                wreg[k] = *(const float4*)(w_z + (r + k*32)*DD + (kc+1)*32 + cc);
        }
        #pragma unroll
        for (int kk = 0; kk < 2; kk++) {
            int k0w = kk*16 + 2*qid;
            int k0a = kc*32 + kk*16 + 2*qid;
            uint32_t bf[4][2];
            #pragma unroll
            for (int n2 = 0; n2 < 4; n2++) {
                const __half* pb = ws + (nB + n2*8 + grp)*40 + k0w;
                bf[n2][0] = *(const uint32_t*)(pb);
                bf[n2][1] = *(const uint32_t*)(pb + 8);
            }
            #pragma unroll
            for (int mt = 0; mt < 4; mt++) {
                const __half* pa = xt + (mB + mt*16 + grp)*136 + k0a;
                uint32_t a0 = *(const uint32_t*)(pa);
                uint32_t a1 = *(const uint32_t*)(pa + 8*136);
                uint32_t a2 = *(const uint32_t*)(pa + 8);
                uint32_t a3 = *(const uint32_t*)(pa + 8*136 + 8);
                #pragma unroll
                for (int n2 = 0; n2 < 4; n2++)
                    mma16(c[mt][n2], a0, a1, a2, a3, bf[n2][0], bf[n2][1]);
            }
        }
        __syncthreads();
    }
    #pragma unroll
    for (int mt = 0; mt < 4; mt++) {
        int p = p0 + mB + mt*16 + grp;
        #pragma unroll
        for (int n2 = 0; n2 < 4; n2++) {
            int d = nB + n2*8 + 2*qid;
            *(float2*)(out_x + (size_t)p*DD + d)     = make_float2(c[mt][n2][0], c[mt][n2][1]);
            *(float2*)(out_x + (size_t)(p+8)*DD + d) = make_float2(c[mt][n2][2], c[mt][n2][3]);
        }
    }
}

// ---------------------------------------------------------------------------
extern "C" void kernel_launch(void* const* d_in, const int* in_sizes, int n_in,
                              void* d_out, int out_size) {
    const float* z       = (const float*)d_in[0];
    const float* mask    = (const float*)d_in[1];
    const float* ln_in_w = (const float*)d_in[2];
    const float* ln_in_b = (const float*)d_in[3];
    const float* w_ab_p  = (const float*)d_in[4];
    const float* b_ab_p  = (const float*)d_in[5];
    const float* w_ab_g  = (const float*)d_in[6];
    const float* b_ab_g  = (const float*)d_in[7];
    const float* w_g     = (const float*)d_in[8];
    const float* ln_out_w= (const float*)d_in[9];
    const float* ln_out_b= (const float*)d_in[10];
    const float* w_z     = (const float*)d_in[11];

    float* out_x = (float*)d_out;
    float* out_g = (out_size >= 2*NP*DD) ? (out_x + (size_t)NP*DD) : nullptr;

    const int projSmem = (128*136 + 3*128*40 + 64*136) * 2;  // 82944
    const int triSmem  = 3 * 2 * 128*40 * 2;                 // 61440
    const int outSmem  = (128*136 + 128*40) * 2;             // 45056
    cudaFuncSetAttribute(proj_kernel, cudaFuncAttributeMaxDynamicSharedMemorySize, projSmem);
    cudaFuncSetAttribute(tri_kernel,  cudaFuncAttributeMaxDynamicSharedMemorySize, triSmem);
    cudaFuncSetAttribute(out_kernel,  cudaFuncAttributeMaxDynamicSharedMemorySize, outSmem);

    prep_w<<<320, 256>>>(w_g, w_ab_p, w_ab_g);
    proj_kernel<<<NP/128, 256, projSmem>>>(z, ln_in_w, ln_in_b, mask, b_ab_p, b_ab_g, out_g);
    tri_kernel<<<dim3(16, 128), 256, triSmem>>>();
    out_kernel<<<NP/128, 256, outSmem>>>(ln_out_w, ln_out_b, w_z, out_x);
}